// round 1
// baseline (speedup 1.0000x reference)
#include <cuda_runtime.h>
#include <math.h>

// Problem constants
#define B  8
#define H  1024
#define W  1024
#define NTOT (B*H*W)          // 8388608
#define NUM_ITER 10

// Tile config
#define TX 32
#define TY 16

// ---------------------------------------------------------------------------
// Scratch buffers (allocation-free: __device__ globals)
// ---------------------------------------------------------------------------
__device__ float g_prob [NTOT];   // sigmoid(pred), persists for reductions
__device__ float g_skelP[NTOT];   // skeleton of pred
__device__ float g_skelT[NTOT];   // skeleton of target
__device__ float g_bufA [NTOT];   // ping-pong eroded image
__device__ float g_bufB [NTOT];   // ping-pong eroded image
__device__ double g_sums[7];      // 0: sp*t  1: sp  2: st*p  3: st  4: p*t  5: p  6: t

__global__ void zero_sums() {
    if (threadIdx.x < 7) g_sums[threadIdx.x] = 0.0;
}

// ---------------------------------------------------------------------------
// Init kernel: base = sigmoid(pred) or float(target)
//   writes base image and skel0 = relu(base - dilate(erode(base)))
//   erode = min over 5-point cross (pad +inf), dilate = max over 3x3 (pad -inf)
// Radius needed: 2.
// ---------------------------------------------------------------------------
#define R2 2
#define SW2 (TX + 2*R2)   // 36
#define SH2 (TY + 2*R2)   // 20

template<bool IS_PRED>
__global__ __launch_bounds__(TX*TY)
void init_kernel(const float* __restrict__ predIn, const int* __restrict__ targIn,
                 float* __restrict__ baseOut, float* __restrict__ skelOut)
{
    __shared__ float s0[SH2][SW2];   // base (+inf outside image)
    __shared__ float s1[SH2][SW2];   // e = erode(base) (-inf outside image)

    const int b  = blockIdx.z;
    const int x0 = blockIdx.x * TX;
    const int y0 = blockIdx.y * TY;
    const int tid = threadIdx.y * TX + threadIdx.x;
    const size_t imgOff = (size_t)b * H * W;

    // load base with halo; OOB -> +inf (neutral for erode)
    for (int i = tid; i < SH2*SW2; i += TX*TY) {
        int ly = i / SW2, lx = i % SW2;
        int gy = y0 + ly - R2, gx = x0 + lx - R2;
        float v = INFINITY;
        if ((unsigned)gy < H && (unsigned)gx < W) {
            if (IS_PRED) {
                float x = predIn[imgOff + (size_t)gy * W + gx];
                v = 1.0f / (1.0f + expf(-x));
            } else {
                v = (float)targIn[imgOff + (size_t)gy * W + gx];
            }
        }
        s0[ly][lx] = v;
    }
    __syncthreads();

    // stage: e = erode(base) over inner region; invalid coords -> -inf (neutral for dilate)
    const int IH = SH2 - 2, IW = SW2 - 2;   // 18 x 34
    for (int i = tid; i < IH*IW; i += TX*TY) {
        int ly = i / IW + 1, lx = i % IW + 1;
        int gy = y0 + ly - R2, gx = x0 + lx - R2;
        float v = -INFINITY;
        if ((unsigned)gy < H && (unsigned)gx < W) {
            float c  = s0[ly][lx];
            float vv = fminf(fminf(s0[ly-1][lx], s0[ly+1][lx]), c);
            float hh = fminf(fminf(s0[ly][lx-1], s0[ly][lx+1]), c);
            v = fminf(vv, hh);
        }
        s1[ly][lx] = v;
    }
    __syncthreads();

    // final: d = dilate(e) 3x3; skel0 = relu(base - d); write base + skel
    {
        const int ly = threadIdx.y + R2, lx = threadIdx.x + R2;
        const int gy = y0 + threadIdx.y, gx = x0 + threadIdx.x;  // always valid (1024 % tile == 0)
        float d = -INFINITY;
        #pragma unroll
        for (int dy = -1; dy <= 1; dy++)
            #pragma unroll
            for (int dx = -1; dx <= 1; dx++)
                d = fmaxf(d, s1[ly+dy][lx+dx]);
        float base = s0[ly][lx];
        size_t idx = imgOff + (size_t)gy * W + gx;
        baseOut[idx] = base;
        skelOut[idx] = fmaxf(base - d, 0.0f);
    }
}

// ---------------------------------------------------------------------------
// One full skeleton iteration, fused:
//   img_e = erode(imgIn)
//   t     = erode(img_e)
//   d     = dilate(t)
//   delta = relu(img_e - d)
//   skel += relu(delta - skel*delta)
//   imgOut = img_e
// Radius needed: 3.
// ---------------------------------------------------------------------------
#define R3 3
#define SW3 (TX + 2*R3)   // 38
#define SH3 (TY + 2*R3)   // 22

__global__ __launch_bounds__(TX*TY)
void iter_kernel(const float* __restrict__ imgIn, float* __restrict__ imgOut,
                 float* __restrict__ skel)
{
    __shared__ float s0[SH3][SW3];   // img, then reused for t
    __shared__ float s1[SH3][SW3];   // e = erode(img)

    const int b  = blockIdx.z;
    const int x0 = blockIdx.x * TX;
    const int y0 = blockIdx.y * TY;
    const int tid = threadIdx.y * TX + threadIdx.x;
    const size_t imgOff = (size_t)b * H * W;
    const float* img = imgIn + imgOff;

    // load img with halo; OOB -> +inf
    for (int i = tid; i < SH3*SW3; i += TX*TY) {
        int ly = i / SW3, lx = i % SW3;
        int gy = y0 + ly - R3, gx = x0 + lx - R3;
        float v = INFINITY;
        if ((unsigned)gy < H && (unsigned)gx < W)
            v = img[(size_t)gy * W + gx];
        s0[ly][lx] = v;
    }
    __syncthreads();

    // stage 1: e = erode(img); invalid -> +inf (feeds erode stage 2)
    {
        const int IH = SH3 - 2, IW = SW3 - 2;   // 20 x 36
        for (int i = tid; i < IH*IW; i += TX*TY) {
            int ly = i / IW + 1, lx = i % IW + 1;
            int gy = y0 + ly - R3, gx = x0 + lx - R3;
            float v = INFINITY;
            if ((unsigned)gy < H && (unsigned)gx < W) {
                float c  = s0[ly][lx];
                float vv = fminf(fminf(s0[ly-1][lx], s0[ly+1][lx]), c);
                float hh = fminf(fminf(s0[ly][lx-1], s0[ly][lx+1]), c);
                v = fminf(vv, hh);
            }
            s1[ly][lx] = v;
        }
    }
    __syncthreads();

    // stage 2: t = erode(e) -> overwrite s0; invalid -> -inf (feeds dilate)
    {
        const int IH = SH3 - 4, IW = SW3 - 4;   // 18 x 34
        for (int i = tid; i < IH*IW; i += TX*TY) {
            int ly = i / IW + 2, lx = i % IW + 2;
            int gy = y0 + ly - R3, gx = x0 + lx - R3;
            float v = -INFINITY;
            if ((unsigned)gy < H && (unsigned)gx < W) {
                float c  = s1[ly][lx];
                float vv = fminf(fminf(s1[ly-1][lx], s1[ly+1][lx]), c);
                float hh = fminf(fminf(s1[ly][lx-1], s1[ly][lx+1]), c);
                v = fminf(vv, hh);
            }
            s0[ly][lx] = v;
        }
    }
    __syncthreads();

    // final: d = dilate(t); delta; skel update; write eroded image
    {
        const int ly = threadIdx.y + R3, lx = threadIdx.x + R3;
        const int gy = y0 + threadIdx.y, gx = x0 + threadIdx.x;
        float d = -INFINITY;
        #pragma unroll
        for (int dy = -1; dy <= 1; dy++)
            #pragma unroll
            for (int dx = -1; dx <= 1; dx++)
                d = fmaxf(d, s0[ly+dy][lx+dx]);
        float e = s1[ly][lx];
        float delta = fmaxf(e - d, 0.0f);
        size_t idx = imgOff + (size_t)gy * W + gx;
        float s = skel[idx];
        imgOut[idx] = e;
        skel[idx]   = s + fmaxf(delta - s * delta, 0.0f);
    }
}

// ---------------------------------------------------------------------------
// Reduction: 7 sums over 8M elements, vectorized, block-reduce + double atomics
// ---------------------------------------------------------------------------
#define RED_BLOCKS 2048
#define RED_THREADS 256

__global__ __launch_bounds__(RED_THREADS)
void reduce_kernel(const int* __restrict__ targ)
{
    const int NV = NTOT / 4;
    const float4* p4  = (const float4*)g_prob;
    const float4* sp4 = (const float4*)g_skelP;
    const float4* st4 = (const float4*)g_skelT;
    const int4*   t4  = (const int4*)targ;

    float a0 = 0.f, a1 = 0.f, a2 = 0.f, a3 = 0.f, a4 = 0.f, a5 = 0.f, a6 = 0.f;

    for (int v = blockIdx.x * RED_THREADS + threadIdx.x; v < NV;
         v += gridDim.x * RED_THREADS) {
        float4 p  = p4[v];
        float4 sp = sp4[v];
        float4 st = st4[v];
        int4   ti = t4[v];
        float tx = (float)ti.x, ty = (float)ti.y, tz = (float)ti.z, tw = (float)ti.w;

        a0 += sp.x*tx + sp.y*ty + sp.z*tz + sp.w*tw;   // skelP * target
        a1 += sp.x + sp.y + sp.z + sp.w;               // skelP
        a2 += st.x*p.x + st.y*p.y + st.z*p.z + st.w*p.w; // skelT * prob
        a3 += st.x + st.y + st.z + st.w;               // skelT
        a4 += p.x*tx + p.y*ty + p.z*tz + p.w*tw;       // prob * target
        a5 += p.x + p.y + p.z + p.w;                   // prob
        a6 += tx + ty + tz + tw;                       // target
    }

    // warp reduce
    #pragma unroll
    for (int off = 16; off > 0; off >>= 1) {
        a0 += __shfl_down_sync(0xFFFFFFFF, a0, off);
        a1 += __shfl_down_sync(0xFFFFFFFF, a1, off);
        a2 += __shfl_down_sync(0xFFFFFFFF, a2, off);
        a3 += __shfl_down_sync(0xFFFFFFFF, a3, off);
        a4 += __shfl_down_sync(0xFFFFFFFF, a4, off);
        a5 += __shfl_down_sync(0xFFFFFFFF, a5, off);
        a6 += __shfl_down_sync(0xFFFFFFFF, a6, off);
    }

    __shared__ double sacc[7][RED_THREADS/32];
    int warp = threadIdx.x >> 5, lane = threadIdx.x & 31;
    if (lane == 0) {
        sacc[0][warp] = a0; sacc[1][warp] = a1; sacc[2][warp] = a2;
        sacc[3][warp] = a3; sacc[4][warp] = a4; sacc[5][warp] = a5;
        sacc[6][warp] = a6;
    }
    __syncthreads();
    if (threadIdx.x < 7) {
        double s = 0.0;
        #pragma unroll
        for (int wv = 0; wv < RED_THREADS/32; wv++) s += sacc[threadIdx.x][wv];
        atomicAdd(&g_sums[threadIdx.x], s);
    }
}

__global__ void finalize_kernel(float* __restrict__ out)
{
    double S_spt = g_sums[0], S_sp = g_sums[1];
    double S_stp = g_sums[2], S_st = g_sums[3];
    double S_pt  = g_sums[4], S_p  = g_sums[5], S_t = g_sums[6];

    const double SMOOTH = 1.0;
    double tprec = (S_spt + SMOOTH) / (S_sp + SMOOTH);
    double tsens = (S_stp + SMOOTH) / (S_st + SMOOTH);
    double cl    = 2.0 * tprec * tsens / (tprec + tsens + 1e-7);
    double dice  = (2.0 * S_pt + SMOOTH) / (S_p + S_t + SMOOTH);
    double comb  = 0.5 * dice + 0.5 * cl;
    out[0] = (float)(1.0 - comb);
}

// ---------------------------------------------------------------------------
// Launch
// ---------------------------------------------------------------------------
extern "C" void kernel_launch(void* const* d_in, const int* in_sizes, int n_in,
                              void* d_out, int out_size)
{
    const float* pred = (const float*)d_in[0];
    const int*   targ = (const int*)d_in[1];
    float* out = (float*)d_out;

    float *prob, *skelP, *skelT, *bufA, *bufB;
    cudaGetSymbolAddress((void**)&prob,  g_prob);
    cudaGetSymbolAddress((void**)&skelP, g_skelP);
    cudaGetSymbolAddress((void**)&skelT, g_skelT);
    cudaGetSymbolAddress((void**)&bufA,  g_bufA);
    cudaGetSymbolAddress((void**)&bufB,  g_bufB);

    dim3 blk(TX, TY);
    dim3 grd(W / TX, H / TY, B);

    zero_sums<<<1, 32>>>();

    // ---- pred skeleton ----
    init_kernel<true><<<grd, blk>>>(pred, nullptr, prob, skelP);
    {
        const float* in = prob;
        float* ob = bufB;
        for (int i = 0; i < NUM_ITER; i++) {
            iter_kernel<<<grd, blk>>>(in, ob, skelP);
            in = ob;
            ob = (ob == bufB) ? bufA : bufB;
        }
    }

    // ---- target skeleton ----
    init_kernel<false><<<grd, blk>>>(nullptr, targ, bufA, skelT);
    {
        const float* in = bufA;
        float* ob = bufB;
        for (int i = 0; i < NUM_ITER; i++) {
            iter_kernel<<<grd, blk>>>(in, ob, skelT);
            in = ob;
            ob = (ob == bufB) ? bufA : bufB;
        }
    }

    // ---- reductions + finalize ----
    reduce_kernel<<<RED_BLOCKS, RED_THREADS>>>(targ);
    finalize_kernel<<<1, 1>>>(out);
}

// round 2
// speedup vs baseline: 2.3191x; 2.3191x over previous
#include <cuda_runtime.h>
#include <math.h>

// Problem constants
#define B  8
#define H  1024
#define W  1024
#define NTOT (B*H*W)
#define NUM_ITER 10

// Tile config: 64x16 outputs per 256-thread block, float4 per thread
#define TW 64
#define TH 16
#define NT 256

#define SW 72          // shared row width (floats): 64 + 4 halo each side
#define SHI 22         // iter kernel rows: 16 + 3 halo each side
#define SHN 20         // init kernel rows: 16 + 2 halo each side

// ---------------------------------------------------------------------------
// Scratch (allocation-free)
// ---------------------------------------------------------------------------
__device__ float g_prob [NTOT];
__device__ float g_skelP[NTOT];
__device__ float g_skelT[NTOT];
__device__ float g_bufA [NTOT];
__device__ float g_bufB [NTOT];
__device__ double g_sums[7];   // 0:sp*t 1:sp 2:st*p 3:st 4:p*t 5:p 6:t

__global__ void zero_sums() { if (threadIdx.x < 7) g_sums[threadIdx.x] = 0.0; }

// ---------------------------------------------------------------------------
// Helpers
// ---------------------------------------------------------------------------
__device__ __forceinline__ float4 ld4(const float* p) { return *(const float4*)p; }
__device__ __forceinline__ void   st4(float* p, float4 v) { *(float4*)p = v; }

// 5-point-cross erode (min of center, up, down, left, right)
__device__ __forceinline__ float4 cross_min(float4 u, float4 c, float4 d, float l, float r) {
    float4 m;
    m.x = fminf(fminf(u.x, d.x), fminf(c.x, fminf(l,   c.y)));
    m.y = fminf(fminf(u.y, d.y), fminf(c.y, fminf(c.x, c.z)));
    m.z = fminf(fminf(u.z, d.z), fminf(c.z, fminf(c.y, c.w)));
    m.w = fminf(fminf(u.w, d.w), fminf(c.w, fminf(c.z, r  )));
    return m;
}

// horizontal 3-max of a row
__device__ __forceinline__ float4 row_max3(float4 c, float l, float r) {
    float4 m;
    m.x = fmaxf(l,   fmaxf(c.x, c.y));
    m.y = fmaxf(c.x, fmaxf(c.y, c.z));
    m.z = fmaxf(c.y, fmaxf(c.z, c.w));
    m.w = fmaxf(c.z, fmaxf(c.w, r  ));
    return m;
}

__device__ __forceinline__ void mask_oob(float4& v, int gy, int gx, float pad) {
    if ((unsigned)gy >= H) { v.x = v.y = v.z = v.w = pad; return; }
    if ((unsigned)(gx+0) >= W) v.x = pad;
    if ((unsigned)(gx+1) >= W) v.y = pad;
    if ((unsigned)(gx+2) >= W) v.z = pad;
    if ((unsigned)(gx+3) >= W) v.w = pad;
}

// ---------------------------------------------------------------------------
// Fused skeleton iteration:
//   e = erode(img); t = erode(e); d = dilate3x3(t)
//   delta = relu(e - d); skel += relu(delta - skel*delta); imgOut = e
// ---------------------------------------------------------------------------
template<bool BORDER>
__device__ __forceinline__ void iter_impl(
    const float* __restrict__ img, float* __restrict__ imgOut,
    float* __restrict__ skel, int x0, int y0, float* s0, float* s1, int tid)
{
    // ---- load img: rows 0..21 (gy=y0-3+r), float4 cells 0..17 (gx=x0-4+4c)
    for (int i = tid; i < SHI*18; i += NT) {
        int r = i / 18, c4 = (i - r*18) * 4;
        int gy = y0 - 3 + r, gx = x0 - 4 + c4;
        float4 v;
        if (!BORDER) {
            v = ld4(&img[gy*W + gx]);
        } else {
            v = make_float4(INFINITY, INFINITY, INFINITY, INFINITY);
            if ((unsigned)gy < H) {
                const float* row = &img[gy*W];
                if ((unsigned)(gx+0) < W) v.x = row[gx+0];
                if ((unsigned)(gx+1) < W) v.y = row[gx+1];
                if ((unsigned)(gx+2) < W) v.z = row[gx+2];
                if ((unsigned)(gx+3) < W) v.w = row[gx+3];
            }
        }
        st4(&s0[r*SW + c4], v);
    }
    __syncthreads();

    // ---- stage 1: e = erode(img), rows 1..20, cells 0..17; OOB -> +inf
    for (int i = tid; i < 20*18; i += NT) {
        int r = 1 + i / 18, c4 = (i % 18) * 4;
        int o = r*SW + c4;
        float4 e = cross_min(ld4(&s0[o-SW]), ld4(&s0[o]), ld4(&s0[o+SW]),
                             s0[o-1], s0[o+4]);
        if (BORDER) mask_oob(e, y0-3+r, x0-4+c4, INFINITY);
        st4(&s1[o], e);
    }
    __syncthreads();

    // ---- stage 2: t = erode(e) -> s0, rows 2..19, cells 0..17; OOB -> -inf
    for (int i = tid; i < 18*18; i += NT) {
        int r = 2 + i / 18, c4 = (i % 18) * 4;
        int o = r*SW + c4;
        float4 t = cross_min(ld4(&s1[o-SW]), ld4(&s1[o]), ld4(&s1[o+SW]),
                             s1[o-1], s1[o+4]);
        if (BORDER) mask_oob(t, y0-3+r, x0-4+c4, -INFINITY);
        st4(&s0[o], t);
    }
    __syncthreads();

    // ---- final: one float4 per thread, rows 3..18, cells 1..16
    {
        int r  = 3 + (tid >> 4);
        int c4 = ((tid & 15) + 1) * 4;
        int o  = r*SW + c4;
        float4 m0 = row_max3(ld4(&s0[o-SW]), s0[o-SW-1], s0[o-SW+4]);
        float4 m1 = row_max3(ld4(&s0[o   ]), s0[o   -1], s0[o   +4]);
        float4 m2 = row_max3(ld4(&s0[o+SW]), s0[o+SW-1], s0[o+SW+4]);
        float4 d;
        d.x = fmaxf(m0.x, fmaxf(m1.x, m2.x));
        d.y = fmaxf(m0.y, fmaxf(m1.y, m2.y));
        d.z = fmaxf(m0.z, fmaxf(m1.z, m2.z));
        d.w = fmaxf(m0.w, fmaxf(m1.w, m2.w));
        float4 e = ld4(&s1[o]);
        float4 dl;
        dl.x = fmaxf(e.x - d.x, 0.f);
        dl.y = fmaxf(e.y - d.y, 0.f);
        dl.z = fmaxf(e.z - d.z, 0.f);
        dl.w = fmaxf(e.w - d.w, 0.f);
        size_t idx = (size_t)(y0 + r - 3) * W + (x0 + c4 - 4);
        float4 s = ld4(&skel[idx]);
        float4 ns;
        ns.x = s.x + fmaxf(dl.x - s.x*dl.x, 0.f);
        ns.y = s.y + fmaxf(dl.y - s.y*dl.y, 0.f);
        ns.z = s.z + fmaxf(dl.z - s.z*dl.z, 0.f);
        ns.w = s.w + fmaxf(dl.w - s.w*dl.w, 0.f);
        st4(&imgOut[idx], e);
        st4(&skel[idx], ns);
    }
}

__global__ __launch_bounds__(NT)
void iter_kernel(const float* __restrict__ imgIn, float* __restrict__ imgOut,
                 float* __restrict__ skel)
{
    __shared__ float s0[SHI*SW];
    __shared__ float s1[SHI*SW];
    int x0 = blockIdx.x * TW, y0 = blockIdx.y * TH;
    size_t off = (size_t)blockIdx.z * H * W;
    int tid = threadIdx.x;
    bool border = (blockIdx.x == 0) | (blockIdx.x == gridDim.x-1) |
                  (blockIdx.y == 0) | (blockIdx.y == gridDim.y-1);
    if (border) iter_impl<true >(imgIn+off, imgOut+off, skel+off, x0, y0, s0, s1, tid);
    else        iter_impl<false>(imgIn+off, imgOut+off, skel+off, x0, y0, s0, s1, tid);
}

// ---------------------------------------------------------------------------
// Init: base = sigmoid(pred) | float(target)
//   e = erode(base); d = dilate3x3(e); skel0 = relu(base - d); write base+skel0
// ---------------------------------------------------------------------------
template<bool IS_PRED, bool BORDER>
__device__ __forceinline__ void init_impl(
    const float* __restrict__ pred, const int* __restrict__ targ,
    float* __restrict__ baseOut, float* __restrict__ skelOut,
    int x0, int y0, float* s0, float* s1, int tid)
{
    // ---- load base: rows 0..19 (gy=y0-2+r), cells 0..17
    for (int i = tid; i < SHN*18; i += NT) {
        int r = i / 18, c4 = (i - r*18) * 4;
        int gy = y0 - 2 + r, gx = x0 - 4 + c4;
        float4 v;
        if (!BORDER) {
            if (IS_PRED) {
                float4 x = ld4(&pred[gy*W + gx]);
                v.x = 1.f / (1.f + __expf(-x.x));
                v.y = 1.f / (1.f + __expf(-x.y));
                v.z = 1.f / (1.f + __expf(-x.z));
                v.w = 1.f / (1.f + __expf(-x.w));
            } else {
                int4 t = *(const int4*)&targ[gy*W + gx];
                v = make_float4((float)t.x, (float)t.y, (float)t.z, (float)t.w);
            }
        } else {
            v = make_float4(INFINITY, INFINITY, INFINITY, INFINITY);
            if ((unsigned)gy < H) {
                #pragma unroll
                for (int k = 0; k < 4; k++) {
                    float* vk = k==0 ? &v.x : k==1 ? &v.y : k==2 ? &v.z : &v.w;
                    if ((unsigned)(gx+k) < W) {
                        if (IS_PRED) { float x = pred[gy*W + gx + k]; *vk = 1.f/(1.f+__expf(-x)); }
                        else         { *vk = (float)targ[gy*W + gx + k]; }
                    }
                }
            }
        }
        st4(&s0[r*SW + c4], v);
    }
    __syncthreads();

    // ---- e = erode(base), rows 1..18, cells 0..17; OOB -> -inf (feeds dilate)
    for (int i = tid; i < 18*18; i += NT) {
        int r = 1 + i / 18, c4 = (i % 18) * 4;
        int o = r*SW + c4;
        float4 e = cross_min(ld4(&s0[o-SW]), ld4(&s0[o]), ld4(&s0[o+SW]),
                             s0[o-1], s0[o+4]);
        if (BORDER) mask_oob(e, y0-2+r, x0-4+c4, -INFINITY);
        st4(&s1[o], e);
    }
    __syncthreads();

    // ---- final: rows 2..17, cells 1..16
    {
        int r  = 2 + (tid >> 4);
        int c4 = ((tid & 15) + 1) * 4;
        int o  = r*SW + c4;
        float4 m0 = row_max3(ld4(&s1[o-SW]), s1[o-SW-1], s1[o-SW+4]);
        float4 m1 = row_max3(ld4(&s1[o   ]), s1[o   -1], s1[o   +4]);
        float4 m2 = row_max3(ld4(&s1[o+SW]), s1[o+SW-1], s1[o+SW+4]);
        float4 d;
        d.x = fmaxf(m0.x, fmaxf(m1.x, m2.x));
        d.y = fmaxf(m0.y, fmaxf(m1.y, m2.y));
        d.z = fmaxf(m0.z, fmaxf(m1.z, m2.z));
        d.w = fmaxf(m0.w, fmaxf(m1.w, m2.w));
        float4 base = ld4(&s0[o]);
        float4 sk;
        sk.x = fmaxf(base.x - d.x, 0.f);
        sk.y = fmaxf(base.y - d.y, 0.f);
        sk.z = fmaxf(base.z - d.z, 0.f);
        sk.w = fmaxf(base.w - d.w, 0.f);
        size_t idx = (size_t)(y0 + r - 2) * W + (x0 + c4 - 4);
        st4(&baseOut[idx], base);
        st4(&skelOut[idx], sk);
    }
}

template<bool IS_PRED>
__global__ __launch_bounds__(NT)
void init_kernel(const float* __restrict__ pred, const int* __restrict__ targ,
                 float* __restrict__ baseOut, float* __restrict__ skelOut)
{
    __shared__ float s0[SHN*SW];
    __shared__ float s1[SHN*SW];
    int x0 = blockIdx.x * TW, y0 = blockIdx.y * TH;
    size_t off = (size_t)blockIdx.z * H * W;
    int tid = threadIdx.x;
    const float* p = IS_PRED ? pred + off : nullptr;
    const int*   t = IS_PRED ? nullptr : targ + off;
    bool border = (blockIdx.x == 0) | (blockIdx.x == gridDim.x-1) |
                  (blockIdx.y == 0) | (blockIdx.y == gridDim.y-1);
    if (border) init_impl<IS_PRED, true >(p, t, baseOut+off, skelOut+off, x0, y0, s0, s1, tid);
    else        init_impl<IS_PRED, false>(p, t, baseOut+off, skelOut+off, x0, y0, s0, s1, tid);
}

// ---------------------------------------------------------------------------
// Reduction: 7 sums over 8M elements
// ---------------------------------------------------------------------------
#define RED_BLOCKS 2048
#define RED_THREADS 256

__global__ __launch_bounds__(RED_THREADS)
void reduce_kernel(const int* __restrict__ targ)
{
    const int NV = NTOT / 4;
    const float4* p4  = (const float4*)g_prob;
    const float4* sp4 = (const float4*)g_skelP;
    const float4* st4p = (const float4*)g_skelT;
    const int4*   t4  = (const int4*)targ;

    float a0=0.f, a1=0.f, a2=0.f, a3=0.f, a4=0.f, a5=0.f, a6=0.f;

    for (int v = blockIdx.x * RED_THREADS + threadIdx.x; v < NV;
         v += gridDim.x * RED_THREADS) {
        float4 p  = p4[v];
        float4 sp = sp4[v];
        float4 st = st4p[v];
        int4   ti = t4[v];
        float tx = (float)ti.x, ty = (float)ti.y, tz = (float)ti.z, tw = (float)ti.w;

        a0 += sp.x*tx + sp.y*ty + sp.z*tz + sp.w*tw;
        a1 += sp.x + sp.y + sp.z + sp.w;
        a2 += st.x*p.x + st.y*p.y + st.z*p.z + st.w*p.w;
        a3 += st.x + st.y + st.z + st.w;
        a4 += p.x*tx + p.y*ty + p.z*tz + p.w*tw;
        a5 += p.x + p.y + p.z + p.w;
        a6 += tx + ty + tz + tw;
    }

    #pragma unroll
    for (int off = 16; off > 0; off >>= 1) {
        a0 += __shfl_down_sync(0xFFFFFFFF, a0, off);
        a1 += __shfl_down_sync(0xFFFFFFFF, a1, off);
        a2 += __shfl_down_sync(0xFFFFFFFF, a2, off);
        a3 += __shfl_down_sync(0xFFFFFFFF, a3, off);
        a4 += __shfl_down_sync(0xFFFFFFFF, a4, off);
        a5 += __shfl_down_sync(0xFFFFFFFF, a5, off);
        a6 += __shfl_down_sync(0xFFFFFFFF, a6, off);
    }

    __shared__ double sacc[7][RED_THREADS/32];
    int warp = threadIdx.x >> 5, lane = threadIdx.x & 31;
    if (lane == 0) {
        sacc[0][warp]=a0; sacc[1][warp]=a1; sacc[2][warp]=a2;
        sacc[3][warp]=a3; sacc[4][warp]=a4; sacc[5][warp]=a5; sacc[6][warp]=a6;
    }
    __syncthreads();
    if (threadIdx.x < 7) {
        double s = 0.0;
        #pragma unroll
        for (int wv = 0; wv < RED_THREADS/32; wv++) s += sacc[threadIdx.x][wv];
        atomicAdd(&g_sums[threadIdx.x], s);
    }
}

__global__ void finalize_kernel(float* __restrict__ out)
{
    double S_spt=g_sums[0], S_sp=g_sums[1], S_stp=g_sums[2], S_st=g_sums[3];
    double S_pt =g_sums[4], S_p =g_sums[5], S_t =g_sums[6];
    const double SMOOTH = 1.0;
    double tprec = (S_spt + SMOOTH) / (S_sp + SMOOTH);
    double tsens = (S_stp + SMOOTH) / (S_st + SMOOTH);
    double cl    = 2.0 * tprec * tsens / (tprec + tsens + 1e-7);
    double dice  = (2.0 * S_pt + SMOOTH) / (S_p + S_t + SMOOTH);
    out[0] = (float)(1.0 - (0.5 * dice + 0.5 * cl));
}

// ---------------------------------------------------------------------------
// Launch
// ---------------------------------------------------------------------------
extern "C" void kernel_launch(void* const* d_in, const int* in_sizes, int n_in,
                              void* d_out, int out_size)
{
    const float* pred = (const float*)d_in[0];
    const int*   targ = (const int*)d_in[1];
    float* out = (float*)d_out;

    float *prob, *skelP, *skelT, *bufA, *bufB;
    cudaGetSymbolAddress((void**)&prob,  g_prob);
    cudaGetSymbolAddress((void**)&skelP, g_skelP);
    cudaGetSymbolAddress((void**)&skelT, g_skelT);
    cudaGetSymbolAddress((void**)&bufA,  g_bufA);
    cudaGetSymbolAddress((void**)&bufB,  g_bufB);

    dim3 grd(W / TW, H / TH, B);   // 16 x 64 x 8

    zero_sums<<<1, 32>>>();

    // ---- pred skeleton ----
    init_kernel<true><<<grd, NT>>>(pred, nullptr, prob, skelP);
    {
        const float* in = prob;
        float* ob = bufB;
        for (int i = 0; i < NUM_ITER; i++) {
            iter_kernel<<<grd, NT>>>(in, ob, skelP);
            in = ob;
            ob = (ob == bufB) ? bufA : bufB;
        }
    }

    // ---- target skeleton ----
    init_kernel<false><<<grd, NT>>>(nullptr, targ, bufA, skelT);
    {
        const float* in = bufA;
        float* ob = bufB;
        for (int i = 0; i < NUM_ITER; i++) {
            iter_kernel<<<grd, NT>>>(in, ob, skelT);
            in = ob;
            ob = (ob == bufB) ? bufA : bufB;
        }
    }

    reduce_kernel<<<RED_BLOCKS, RED_THREADS>>>(targ);
    finalize_kernel<<<1, 1>>>(out);
}

// round 3
// speedup vs baseline: 2.3197x; 1.0003x over previous
#include <cuda_runtime.h>
#include <math.h>

// Problem constants
#define B  8
#define H  1024
#define W  1024
#define NTOT (B*H*W)
#define NUM_ITER 10

#define NT 256          // threads per block (= W/4)
#define SH 16           // strip height (output rows per block)

#define PINF  __int_as_float(0x7f800000)
#define NINF  __int_as_float(0xff800000)

// ---------------------------------------------------------------------------
// Scratch (allocation-free)
// ---------------------------------------------------------------------------
__device__ float g_prob [NTOT];
__device__ float g_skelP[NTOT];
__device__ float g_skelT[NTOT];
__device__ float g_bufA [NTOT];
__device__ float g_bufB [NTOT];
__device__ double g_sums[7];   // 0:sp*t 1:sp 2:st*p 3:st 4:p*t 5:p 6:t

__global__ void zero_sums() { if (threadIdx.x < 7) g_sums[threadIdx.x] = 0.0; }

// ---------------------------------------------------------------------------
// Helpers
// ---------------------------------------------------------------------------
__device__ __forceinline__ float4 ld4(const float* p) { return *(const float4*)p; }
__device__ __forceinline__ void   st4(float* p, float4 v) { *(float4*)p = v; }

// cross erode: min(center, up, down, left, right) componentwise for a float4 row
__device__ __forceinline__ float4 cross_min(float4 u, float4 c, float4 d, float l, float r) {
    float4 m;
    m.x = fminf(fminf(u.x, d.x), fminf(c.x, fminf(l,   c.y)));
    m.y = fminf(fminf(u.y, d.y), fminf(c.y, fminf(c.x, c.z)));
    m.z = fminf(fminf(u.z, d.z), fminf(c.z, fminf(c.y, c.w)));
    m.w = fminf(fminf(u.w, d.w), fminf(c.w, fminf(c.z, r  )));
    return m;
}

// horizontal 3-max of a row
__device__ __forceinline__ float4 row_max3(float4 c, float l, float r) {
    float4 m;
    m.x = fmaxf(l,   fmaxf(c.x, c.y));
    m.y = fmaxf(c.x, fmaxf(c.y, c.z));
    m.z = fmaxf(c.y, fmaxf(c.z, c.w));
    m.w = fmaxf(c.z, fmaxf(c.w, r  ));
    return m;
}

// ---------------------------------------------------------------------------
// Streaming fused skeleton iteration.
// Block = 256 threads = one full 1024-wide row (float4/thread).
// Sweeps rows y0-3 .. y0+SH+5 (25 steps), all stages in register rings.
// Stage rows at step s (li = y0-3+s):
//   load img[li]           (s in [0,21])
//   e[li-2] = erode(img)   (s in [3,22])   -> eW ring8[s&7], bnd ring4[s&3]
//   t[li-4] = erode(e)     (s in [6,23])   -> tT ring2[s&1], bnd ring4[s&3]
//   hm[li-5] = hmax3(t)    (s in [7,24])   -> hmW ring4[s&3]
//   m=li-6: d=vmax3(hm); delta=relu(e-d); skel+=relu(delta-skel*delta);
//           imgOut=e       (s in [9,24])
// Horizontal neighbor scalars cross thread boundaries via tiny shared rings
// (one float2 {x,w} per thread per stage), one __syncthreads per step.
// ---------------------------------------------------------------------------
__global__ __launch_bounds__(NT)
void iter_kernel(const float* __restrict__ imgIn, float* __restrict__ imgOut,
                 float* __restrict__ skel)
{
    __shared__ float2 bImg[4][NT];
    __shared__ float2 bE  [4][NT];
    __shared__ float2 bT  [4][NT];

    const int tid = threadIdx.x;
    const int x4  = tid * 4;
    const int y0  = blockIdx.x * SH;
    const size_t off = (size_t)blockIdx.y * (H * W);
    const float* img = imgIn + off;
    float* outp = imgOut + off;
    float* skp  = skel  + off;

    float4 imgW[4];   // img rows, slot s&3 at load step s
    float4 eW[8];     // e rows, slot s&7 at e step s
    float4 tT[2];     // t rows, slot s&1
    float4 hmW[4];    // hmax rows, slot s&3

    #pragma unroll
    for (int s = 0; s < SH + 9; s++) {
        const int li = y0 - 3 + s;

        // ---- load img row li + publish boundary scalars
        if (s <= 21) {
            float4 v;
            if ((unsigned)li < H) v = ld4(&img[(size_t)li * W + x4]);
            else v = make_float4(PINF, PINF, PINF, PINF);
            imgW[s & 3] = v;
            bImg[s & 3][tid] = make_float2(v.x, v.w);
        }

        // ---- e[j], j = li-2: cross erode of img (pad +inf handled by loads)
        if (s >= 3 && s <= 22) {
            float4 u = imgW[(s - 3) & 3];
            float4 c = imgW[(s - 2) & 3];
            float4 d = imgW[(s - 1) & 3];
            float l = (tid == 0)      ? PINF : bImg[(s - 2) & 3][tid - 1].y;
            float r = (tid == NT - 1) ? PINF : bImg[(s - 2) & 3][tid + 1].x;
            float4 e = cross_min(u, c, d, l, r);
            eW[s & 7] = e;
            bE[s & 3][tid] = make_float2(e.x, e.w);
        }

        // ---- t[k], k = li-4: cross erode of e; OOB rows/cols -> -inf (feeds dilate)
        if (s >= 6 && s <= 23) {
            const int k = li - 4;
            float4 u = eW[(s - 3) & 7];
            float4 c = eW[(s - 2) & 7];
            float4 d = eW[(s - 1) & 7];
            float l = (tid == 0)      ? PINF : bE[(s - 2) & 3][tid - 1].y;
            float r = (tid == NT - 1) ? PINF : bE[(s - 2) & 3][tid + 1].x;
            float4 t = cross_min(u, c, d, l, r);
            if ((unsigned)k >= H) t = make_float4(NINF, NINF, NINF, NINF);
            tT[s & 1] = t;
            bT[s & 3][tid] = make_float2(t.x, t.w);
        }

        // ---- hm[li-5] = horizontal 3-max of t
        if (s >= 7 && s <= 24) {
            float4 t = tT[(s - 1) & 1];
            float l = (tid == 0)      ? NINF : bT[(s - 1) & 3][tid - 1].y;
            float r = (tid == NT - 1) ? NINF : bT[(s - 1) & 3][tid + 1].x;
            hmW[s & 3] = row_max3(t, l, r);
        }

        // ---- output row m = li-6
        if (s >= 9) {
            const int m = li - 6;
            float4 h0 = hmW[(s - 2) & 3];
            float4 h1 = hmW[(s - 1) & 3];
            float4 h2 = hmW[s & 3];
            float4 d4;
            d4.x = fmaxf(h0.x, fmaxf(h1.x, h2.x));
            d4.y = fmaxf(h0.y, fmaxf(h1.y, h2.y));
            d4.z = fmaxf(h0.z, fmaxf(h1.z, h2.z));
            d4.w = fmaxf(h0.w, fmaxf(h1.w, h2.w));
            float4 e = eW[(s - 4) & 7];
            float4 dl;
            dl.x = fmaxf(e.x - d4.x, 0.f);
            dl.y = fmaxf(e.y - d4.y, 0.f);
            dl.z = fmaxf(e.z - d4.z, 0.f);
            dl.w = fmaxf(e.w - d4.w, 0.f);
            size_t idx = (size_t)m * W + x4;
            float4 sv = ld4(&skp[idx]);
            float4 ns;
            ns.x = sv.x + fmaxf(dl.x - sv.x * dl.x, 0.f);
            ns.y = sv.y + fmaxf(dl.y - sv.y * dl.y, 0.f);
            ns.z = sv.z + fmaxf(dl.z - sv.z * dl.z, 0.f);
            ns.w = sv.w + fmaxf(dl.w - sv.w * dl.w, 0.f);
            st4(&outp[idx], e);
            st4(&skp[idx], ns);
        }

        __syncthreads();
    }
}

// ---------------------------------------------------------------------------
// Init: base = sigmoid(pred) | float(target)
//   e = erode(base); d = dilate3x3(e); skel0 = relu(base - d); write base+skel0
// (tiled shared-memory version, runs twice only)
// ---------------------------------------------------------------------------
#define TW 64
#define TH 16
#define SW 72
#define SHN 20

__device__ __forceinline__ void mask_oob(float4& v, int gy, int gx, float pad) {
    if ((unsigned)gy >= H) { v.x = v.y = v.z = v.w = pad; return; }
    if ((unsigned)(gx+0) >= W) v.x = pad;
    if ((unsigned)(gx+1) >= W) v.y = pad;
    if ((unsigned)(gx+2) >= W) v.z = pad;
    if ((unsigned)(gx+3) >= W) v.w = pad;
}

template<bool IS_PRED, bool BORDER>
__device__ __forceinline__ void init_impl(
    const float* __restrict__ pred, const int* __restrict__ targ,
    float* __restrict__ baseOut, float* __restrict__ skelOut,
    int x0, int y0, float* s0, float* s1, int tid)
{
    for (int i = tid; i < SHN*18; i += NT) {
        int r = i / 18, c4 = (i - r*18) * 4;
        int gy = y0 - 2 + r, gx = x0 - 4 + c4;
        float4 v;
        if (!BORDER) {
            if (IS_PRED) {
                float4 x = ld4(&pred[gy*W + gx]);
                v.x = 1.f / (1.f + __expf(-x.x));
                v.y = 1.f / (1.f + __expf(-x.y));
                v.z = 1.f / (1.f + __expf(-x.z));
                v.w = 1.f / (1.f + __expf(-x.w));
            } else {
                int4 t = *(const int4*)&targ[gy*W + gx];
                v = make_float4((float)t.x, (float)t.y, (float)t.z, (float)t.w);
            }
        } else {
            v = make_float4(PINF, PINF, PINF, PINF);
            if ((unsigned)gy < H) {
                #pragma unroll
                for (int k = 0; k < 4; k++) {
                    float* vk = k==0 ? &v.x : k==1 ? &v.y : k==2 ? &v.z : &v.w;
                    if ((unsigned)(gx+k) < W) {
                        if (IS_PRED) { float x = pred[gy*W + gx + k]; *vk = 1.f/(1.f+__expf(-x)); }
                        else         { *vk = (float)targ[gy*W + gx + k]; }
                    }
                }
            }
        }
        st4(&s0[r*SW + c4], v);
    }
    __syncthreads();

    for (int i = tid; i < 18*18; i += NT) {
        int r = 1 + i / 18, c4 = (i % 18) * 4;
        int o = r*SW + c4;
        float4 e = cross_min(ld4(&s0[o-SW]), ld4(&s0[o]), ld4(&s0[o+SW]),
                             s0[o-1], s0[o+4]);
        if (BORDER) mask_oob(e, y0-2+r, x0-4+c4, NINF);
        st4(&s1[o], e);
    }
    __syncthreads();

    {
        int r  = 2 + (tid >> 4);
        int c4 = ((tid & 15) + 1) * 4;
        int o  = r*SW + c4;
        float4 m0 = row_max3(ld4(&s1[o-SW]), s1[o-SW-1], s1[o-SW+4]);
        float4 m1 = row_max3(ld4(&s1[o   ]), s1[o   -1], s1[o   +4]);
        float4 m2 = row_max3(ld4(&s1[o+SW]), s1[o+SW-1], s1[o+SW+4]);
        float4 d;
        d.x = fmaxf(m0.x, fmaxf(m1.x, m2.x));
        d.y = fmaxf(m0.y, fmaxf(m1.y, m2.y));
        d.z = fmaxf(m0.z, fmaxf(m1.z, m2.z));
        d.w = fmaxf(m0.w, fmaxf(m1.w, m2.w));
        float4 base = ld4(&s0[o]);
        float4 sk;
        sk.x = fmaxf(base.x - d.x, 0.f);
        sk.y = fmaxf(base.y - d.y, 0.f);
        sk.z = fmaxf(base.z - d.z, 0.f);
        sk.w = fmaxf(base.w - d.w, 0.f);
        size_t idx = (size_t)(y0 + r - 2) * W + (x0 + c4 - 4);
        st4(&baseOut[idx], base);
        st4(&skelOut[idx], sk);
    }
}

template<bool IS_PRED>
__global__ __launch_bounds__(NT)
void init_kernel(const float* __restrict__ pred, const int* __restrict__ targ,
                 float* __restrict__ baseOut, float* __restrict__ skelOut)
{
    __shared__ float s0[SHN*SW];
    __shared__ float s1[SHN*SW];
    int x0 = blockIdx.x * TW, y0 = blockIdx.y * TH;
    size_t off = (size_t)blockIdx.z * H * W;
    int tid = threadIdx.x;
    const float* p = IS_PRED ? pred + off : nullptr;
    const int*   t = IS_PRED ? nullptr : targ + off;
    bool border = (blockIdx.x == 0) | (blockIdx.x == gridDim.x-1) |
                  (blockIdx.y == 0) | (blockIdx.y == gridDim.y-1);
    if (border) init_impl<IS_PRED, true >(p, t, baseOut+off, skelOut+off, x0, y0, s0, s1, tid);
    else        init_impl<IS_PRED, false>(p, t, baseOut+off, skelOut+off, x0, y0, s0, s1, tid);
}

// ---------------------------------------------------------------------------
// Reduction: 7 sums over 8M elements
// ---------------------------------------------------------------------------
#define RED_BLOCKS 2048
#define RED_THREADS 256

__global__ __launch_bounds__(RED_THREADS)
void reduce_kernel(const int* __restrict__ targ)
{
    const int NV = NTOT / 4;
    const float4* p4   = (const float4*)g_prob;
    const float4* sp4  = (const float4*)g_skelP;
    const float4* st4p = (const float4*)g_skelT;
    const int4*   t4   = (const int4*)targ;

    float a0=0.f, a1=0.f, a2=0.f, a3=0.f, a4=0.f, a5=0.f, a6=0.f;

    for (int v = blockIdx.x * RED_THREADS + threadIdx.x; v < NV;
         v += gridDim.x * RED_THREADS) {
        float4 p  = p4[v];
        float4 sp = sp4[v];
        float4 st = st4p[v];
        int4   ti = t4[v];
        float tx = (float)ti.x, ty = (float)ti.y, tz = (float)ti.z, tw = (float)ti.w;

        a0 += sp.x*tx + sp.y*ty + sp.z*tz + sp.w*tw;
        a1 += sp.x + sp.y + sp.z + sp.w;
        a2 += st.x*p.x + st.y*p.y + st.z*p.z + st.w*p.w;
        a3 += st.x + st.y + st.z + st.w;
        a4 += p.x*tx + p.y*ty + p.z*tz + p.w*tw;
        a5 += p.x + p.y + p.z + p.w;
        a6 += tx + ty + tz + tw;
    }

    #pragma unroll
    for (int off = 16; off > 0; off >>= 1) {
        a0 += __shfl_down_sync(0xFFFFFFFF, a0, off);
        a1 += __shfl_down_sync(0xFFFFFFFF, a1, off);
        a2 += __shfl_down_sync(0xFFFFFFFF, a2, off);
        a3 += __shfl_down_sync(0xFFFFFFFF, a3, off);
        a4 += __shfl_down_sync(0xFFFFFFFF, a4, off);
        a5 += __shfl_down_sync(0xFFFFFFFF, a5, off);
        a6 += __shfl_down_sync(0xFFFFFFFF, a6, off);
    }

    __shared__ double sacc[7][RED_THREADS/32];
    int warp = threadIdx.x >> 5, lane = threadIdx.x & 31;
    if (lane == 0) {
        sacc[0][warp]=a0; sacc[1][warp]=a1; sacc[2][warp]=a2;
        sacc[3][warp]=a3; sacc[4][warp]=a4; sacc[5][warp]=a5; sacc[6][warp]=a6;
    }
    __syncthreads();
    if (threadIdx.x < 7) {
        double s = 0.0;
        #pragma unroll
        for (int wv = 0; wv < RED_THREADS/32; wv++) s += sacc[threadIdx.x][wv];
        atomicAdd(&g_sums[threadIdx.x], s);
    }
}

__global__ void finalize_kernel(float* __restrict__ out)
{
    double S_spt=g_sums[0], S_sp=g_sums[1], S_stp=g_sums[2], S_st=g_sums[3];
    double S_pt =g_sums[4], S_p =g_sums[5], S_t =g_sums[6];
    const double SMOOTH = 1.0;
    double tprec = (S_spt + SMOOTH) / (S_sp + SMOOTH);
    double tsens = (S_stp + SMOOTH) / (S_st + SMOOTH);
    double cl    = 2.0 * tprec * tsens / (tprec + tsens + 1e-7);
    double dice  = (2.0 * S_pt + SMOOTH) / (S_p + S_t + SMOOTH);
    out[0] = (float)(1.0 - (0.5 * dice + 0.5 * cl));
}

// ---------------------------------------------------------------------------
// Launch
// ---------------------------------------------------------------------------
extern "C" void kernel_launch(void* const* d_in, const int* in_sizes, int n_in,
                              void* d_out, int out_size)
{
    const float* pred = (const float*)d_in[0];
    const int*   targ = (const int*)d_in[1];
    float* out = (float*)d_out;

    float *prob, *skelP, *skelT, *bufA, *bufB;
    cudaGetSymbolAddress((void**)&prob,  g_prob);
    cudaGetSymbolAddress((void**)&skelP, g_skelP);
    cudaGetSymbolAddress((void**)&skelT, g_skelT);
    cudaGetSymbolAddress((void**)&bufA,  g_bufA);
    cudaGetSymbolAddress((void**)&bufB,  g_bufB);

    dim3 grdInit(W / TW, H / TH, B);   // 16 x 64 x 8
    dim3 grdIter(H / SH, B);           // 64 x 8 = 512 blocks

    zero_sums<<<1, 32>>>();

    // ---- pred skeleton ----
    init_kernel<true><<<grdInit, NT>>>(pred, nullptr, prob, skelP);
    {
        const float* in = prob;
        float* ob = bufB;
        for (int i = 0; i < NUM_ITER; i++) {
            iter_kernel<<<grdIter, NT>>>(in, ob, skelP);
            in = ob;
            ob = (ob == bufB) ? bufA : bufB;
        }
    }

    // ---- target skeleton ----
    init_kernel<false><<<grdInit, NT>>>(nullptr, targ, bufA, skelT);
    {
        const float* in = bufA;
        float* ob = bufB;
        for (int i = 0; i < NUM_ITER; i++) {
            iter_kernel<<<grdIter, NT>>>(in, ob, skelT);
            in = ob;
            ob = (ob == bufB) ? bufA : bufB;
        }
    }

    reduce_kernel<<<RED_BLOCKS, RED_THREADS>>>(targ);
    finalize_kernel<<<1, 1>>>(out);
}

// round 4
// speedup vs baseline: 2.7935x; 1.2042x over previous
#include <cuda_runtime.h>
#include <math.h>

// Problem constants
#define B  8
#define H  1024
#define W  1024
#define NTOT (B*H*W)

#define NT 256
#define TW 64          // tile width (output)
#define TH 16          // tile height (output)
#define SW 72          // shared row width in floats (64 + 4 halo each side)
#define SH2I 24        // fused-2 iter kernel rows: 16 + 4 halo each side
#define SHN 20         // init kernel rows: 16 + 2 halo each side

#define PINF  __int_as_float(0x7f800000)
#define NINF  __int_as_float(0xff800000)

// ---------------------------------------------------------------------------
// Scratch (allocation-free)
// ---------------------------------------------------------------------------
__device__ float g_prob [NTOT];
__device__ float g_skelP[NTOT];
__device__ float g_skelT[NTOT];
__device__ float g_bufA [NTOT];
__device__ float g_bufB [NTOT];
__device__ double g_sums[7];   // 0:sp*t 1:sp 2:st*p 3:st 4:p*t 5:p 6:t

__global__ void zero_sums() { if (threadIdx.x < 7) g_sums[threadIdx.x] = 0.0; }

// ---------------------------------------------------------------------------
// Helpers
// ---------------------------------------------------------------------------
__device__ __forceinline__ float4 ld4(const float* p) { return *(const float4*)p; }
__device__ __forceinline__ void   st4(float* p, float4 v) { *(float4*)p = v; }

__device__ __forceinline__ float4 cross_min(float4 u, float4 c, float4 d, float l, float r) {
    float4 m;
    m.x = fminf(fminf(u.x, d.x), fminf(c.x, fminf(l,   c.y)));
    m.y = fminf(fminf(u.y, d.y), fminf(c.y, fminf(c.x, c.z)));
    m.z = fminf(fminf(u.z, d.z), fminf(c.z, fminf(c.y, c.w)));
    m.w = fminf(fminf(u.w, d.w), fminf(c.w, fminf(c.z, r  )));
    return m;
}

__device__ __forceinline__ float4 row_max3(float4 c, float l, float r) {
    float4 m;
    m.x = fmaxf(l,   fmaxf(c.x, c.y));
    m.y = fmaxf(c.x, fmaxf(c.y, c.z));
    m.z = fmaxf(c.y, fmaxf(c.z, c.w));
    m.w = fmaxf(c.z, fmaxf(c.w, r  ));
    return m;
}

// 3x3 dilate at shared offset o (row stride SW)
__device__ __forceinline__ float4 dil3x3(const float* s, int o) {
    float4 m0 = row_max3(ld4(&s[o-SW]), s[o-SW-1], s[o-SW+4]);
    float4 m1 = row_max3(ld4(&s[o   ]), s[o   -1], s[o   +4]);
    float4 m2 = row_max3(ld4(&s[o+SW]), s[o+SW-1], s[o+SW+4]);
    float4 d;
    d.x = fmaxf(m0.x, fmaxf(m1.x, m2.x));
    d.y = fmaxf(m0.y, fmaxf(m1.y, m2.y));
    d.z = fmaxf(m0.z, fmaxf(m1.z, m2.z));
    d.w = fmaxf(m0.w, fmaxf(m1.w, m2.w));
    return d;
}

__device__ __forceinline__ void mask_oob(float4& v, int gy, int gx, float pad) {
    if ((unsigned)gy >= H) { v.x = v.y = v.z = v.w = pad; return; }
    if ((unsigned)(gx+0) >= W) v.x = pad;
    if ((unsigned)(gx+1) >= W) v.y = pad;
    if ((unsigned)(gx+2) >= W) v.z = pad;
    if ((unsigned)(gx+3) >= W) v.w = pad;
}

// ---------------------------------------------------------------------------
// Fused DOUBLE skeleton iteration (one launch = 2 iterations):
//   e1 = erode(img); t1 = erode(e1); d1 = dilate(t1)
//   e2 = erode(e1);  t2 = erode(e2); d2 = dilate(t2)
//   skel += relu(d1-chain); skel += relu(d2-chain); imgOut = e2
// Shared buffers: sImg (img, then reused for e2), sE1, sT1, sT2. 24 x 72 each.
// ---------------------------------------------------------------------------
template<bool BORDER, bool WRITE_IMG>
__device__ __forceinline__ void iter2_impl(
    const float* __restrict__ img, float* __restrict__ imgOut,
    float* __restrict__ skel, int x0, int y0,
    float* sImg, float* sE1, float* sT1, float* sT2, int tid)
{
    // ---- load img rows 0..23 (gy = y0-4+r); pad +inf
    for (int i = tid; i < SH2I*18; i += NT) {
        int r = i / 18, c4 = (i - r*18) * 4;
        int gy = y0 - 4 + r, gx = x0 - 4 + c4;
        float4 v;
        if (!BORDER) {
            v = ld4(&img[gy*W + gx]);
        } else {
            v = make_float4(PINF, PINF, PINF, PINF);
            if ((unsigned)gy < H) {
                const float* row = &img[gy*W];
                if ((unsigned)(gx+0) < W) v.x = row[gx+0];
                if ((unsigned)(gx+1) < W) v.y = row[gx+1];
                if ((unsigned)(gx+2) < W) v.z = row[gx+2];
                if ((unsigned)(gx+3) < W) v.w = row[gx+3];
            }
        }
        st4(&sImg[r*SW + c4], v);
    }
    __syncthreads();

    // ---- e1 = erode(img), rows 1..22; OOB -> +inf (feeds erodes)
    for (int i = tid; i < 22*18; i += NT) {
        int r = 1 + i / 18, c4 = (i % 18) * 4;
        int o = r*SW + c4;
        float4 e = cross_min(ld4(&sImg[o-SW]), ld4(&sImg[o]), ld4(&sImg[o+SW]),
                             sImg[o-1], sImg[o+4]);
        if (BORDER) mask_oob(e, y0-4+r, x0-4+c4, PINF);
        st4(&sE1[o], e);
    }
    __syncthreads();

    // ---- t1 = erode(e1) -> sT1 (OOB -inf, feeds dilate)
    //      e2 = erode(e1) -> sImg (OOB +inf, feeds erode)   [img dead now]
    for (int i = tid; i < 20*18; i += NT) {
        int r = 2 + i / 18, c4 = (i % 18) * 4;
        int o = r*SW + c4;
        float4 t = cross_min(ld4(&sE1[o-SW]), ld4(&sE1[o]), ld4(&sE1[o+SW]),
                             sE1[o-1], sE1[o+4]);
        float4 e2 = t;
        if (BORDER) {
            mask_oob(t,  y0-4+r, x0-4+c4, NINF);
            mask_oob(e2, y0-4+r, x0-4+c4, PINF);
        }
        st4(&sT1[o], t);
        st4(&sImg[o], e2);
    }
    __syncthreads();

    // ---- t2 = erode(e2), rows 3..20; OOB -> -inf
    for (int i = tid; i < 18*18; i += NT) {
        int r = 3 + i / 18, c4 = (i % 18) * 4;
        int o = r*SW + c4;
        float4 t = cross_min(ld4(&sImg[o-SW]), ld4(&sImg[o]), ld4(&sImg[o+SW]),
                             sImg[o-1], sImg[o+4]);
        if (BORDER) mask_oob(t, y0-4+r, x0-4+c4, NINF);
        st4(&sT2[o], t);
    }
    __syncthreads();

    // ---- final: rows 4..19, cells 1..16; both skel updates + img write
    {
        int r  = 4 + (tid >> 4);
        int c4 = ((tid & 15) + 1) * 4;
        int o  = r*SW + c4;

        float4 d1 = dil3x3(sT1, o);
        float4 d2 = dil3x3(sT2, o);
        float4 e1 = ld4(&sE1[o]);
        float4 e2 = ld4(&sImg[o]);

        float4 dl1, dl2;
        dl1.x = fmaxf(e1.x - d1.x, 0.f); dl1.y = fmaxf(e1.y - d1.y, 0.f);
        dl1.z = fmaxf(e1.z - d1.z, 0.f); dl1.w = fmaxf(e1.w - d1.w, 0.f);
        dl2.x = fmaxf(e2.x - d2.x, 0.f); dl2.y = fmaxf(e2.y - d2.y, 0.f);
        dl2.z = fmaxf(e2.z - d2.z, 0.f); dl2.w = fmaxf(e2.w - d2.w, 0.f);

        size_t idx = (size_t)(y0 + r - 4) * W + (x0 + c4 - 4);
        float4 s = ld4(&skel[idx]);
        s.x += fmaxf(dl1.x - s.x * dl1.x, 0.f);
        s.y += fmaxf(dl1.y - s.y * dl1.y, 0.f);
        s.z += fmaxf(dl1.z - s.z * dl1.z, 0.f);
        s.w += fmaxf(dl1.w - s.w * dl1.w, 0.f);
        s.x += fmaxf(dl2.x - s.x * dl2.x, 0.f);
        s.y += fmaxf(dl2.y - s.y * dl2.y, 0.f);
        s.z += fmaxf(dl2.z - s.z * dl2.z, 0.f);
        s.w += fmaxf(dl2.w - s.w * dl2.w, 0.f);

        if (WRITE_IMG) st4(&imgOut[idx], e2);
        st4(&skel[idx], s);
    }
}

template<bool WRITE_IMG>
__global__ __launch_bounds__(NT)
void iter2_kernel(const float* __restrict__ imgIn, float* __restrict__ imgOut,
                  float* __restrict__ skel)
{
    __shared__ float sImg[SH2I*SW];
    __shared__ float sE1 [SH2I*SW];
    __shared__ float sT1 [SH2I*SW];
    __shared__ float sT2 [SH2I*SW];
    int x0 = blockIdx.x * TW, y0 = blockIdx.y * TH;
    size_t off = (size_t)blockIdx.z * H * W;
    int tid = threadIdx.x;
    bool border = (blockIdx.x == 0) | (blockIdx.x == gridDim.x-1) |
                  (blockIdx.y == 0) | (blockIdx.y == gridDim.y-1);
    if (border) iter2_impl<true , WRITE_IMG>(imgIn+off, imgOut+off, skel+off, x0, y0, sImg, sE1, sT1, sT2, tid);
    else        iter2_impl<false, WRITE_IMG>(imgIn+off, imgOut+off, skel+off, x0, y0, sImg, sE1, sT1, sT2, tid);
}

// ---------------------------------------------------------------------------
// Init: base = sigmoid(pred) | float(target)
//   e = erode(base); d = dilate3x3(e); skel0 = relu(base - d); write base+skel0
// ---------------------------------------------------------------------------
template<bool IS_PRED, bool BORDER>
__device__ __forceinline__ void init_impl(
    const float* __restrict__ pred, const int* __restrict__ targ,
    float* __restrict__ baseOut, float* __restrict__ skelOut,
    int x0, int y0, float* s0, float* s1, int tid)
{
    for (int i = tid; i < SHN*18; i += NT) {
        int r = i / 18, c4 = (i - r*18) * 4;
        int gy = y0 - 2 + r, gx = x0 - 4 + c4;
        float4 v;
        if (!BORDER) {
            if (IS_PRED) {
                float4 x = ld4(&pred[gy*W + gx]);
                v.x = 1.f / (1.f + __expf(-x.x));
                v.y = 1.f / (1.f + __expf(-x.y));
                v.z = 1.f / (1.f + __expf(-x.z));
                v.w = 1.f / (1.f + __expf(-x.w));
            } else {
                int4 t = *(const int4*)&targ[gy*W + gx];
                v = make_float4((float)t.x, (float)t.y, (float)t.z, (float)t.w);
            }
        } else {
            v = make_float4(PINF, PINF, PINF, PINF);
            if ((unsigned)gy < H) {
                #pragma unroll
                for (int k = 0; k < 4; k++) {
                    float* vk = k==0 ? &v.x : k==1 ? &v.y : k==2 ? &v.z : &v.w;
                    if ((unsigned)(gx+k) < W) {
                        if (IS_PRED) { float x = pred[gy*W + gx + k]; *vk = 1.f/(1.f+__expf(-x)); }
                        else         { *vk = (float)targ[gy*W + gx + k]; }
                    }
                }
            }
        }
        st4(&s0[r*SW + c4], v);
    }
    __syncthreads();

    for (int i = tid; i < 18*18; i += NT) {
        int r = 1 + i / 18, c4 = (i % 18) * 4;
        int o = r*SW + c4;
        float4 e = cross_min(ld4(&s0[o-SW]), ld4(&s0[o]), ld4(&s0[o+SW]),
                             s0[o-1], s0[o+4]);
        if (BORDER) mask_oob(e, y0-2+r, x0-4+c4, NINF);
        st4(&s1[o], e);
    }
    __syncthreads();

    {
        int r  = 2 + (tid >> 4);
        int c4 = ((tid & 15) + 1) * 4;
        int o  = r*SW + c4;
        float4 d = dil3x3(s1, o);
        float4 base = ld4(&s0[o]);
        float4 sk;
        sk.x = fmaxf(base.x - d.x, 0.f);
        sk.y = fmaxf(base.y - d.y, 0.f);
        sk.z = fmaxf(base.z - d.z, 0.f);
        sk.w = fmaxf(base.w - d.w, 0.f);
        size_t idx = (size_t)(y0 + r - 2) * W + (x0 + c4 - 4);
        st4(&baseOut[idx], base);
        st4(&skelOut[idx], sk);
    }
}

template<bool IS_PRED>
__global__ __launch_bounds__(NT)
void init_kernel(const float* __restrict__ pred, const int* __restrict__ targ,
                 float* __restrict__ baseOut, float* __restrict__ skelOut)
{
    __shared__ float s0[SHN*SW];
    __shared__ float s1[SHN*SW];
    int x0 = blockIdx.x * TW, y0 = blockIdx.y * TH;
    size_t off = (size_t)blockIdx.z * H * W;
    int tid = threadIdx.x;
    const float* p = IS_PRED ? pred + off : nullptr;
    const int*   t = IS_PRED ? nullptr : targ + off;
    bool border = (blockIdx.x == 0) | (blockIdx.x == gridDim.x-1) |
                  (blockIdx.y == 0) | (blockIdx.y == gridDim.y-1);
    if (border) init_impl<IS_PRED, true >(p, t, baseOut+off, skelOut+off, x0, y0, s0, s1, tid);
    else        init_impl<IS_PRED, false>(p, t, baseOut+off, skelOut+off, x0, y0, s0, s1, tid);
}

// ---------------------------------------------------------------------------
// Reduction: 7 sums over 8M elements
// ---------------------------------------------------------------------------
#define RED_BLOCKS 2048
#define RED_THREADS 256

__global__ __launch_bounds__(RED_THREADS)
void reduce_kernel(const int* __restrict__ targ)
{
    const int NV = NTOT / 4;
    const float4* p4   = (const float4*)g_prob;
    const float4* sp4  = (const float4*)g_skelP;
    const float4* st4p = (const float4*)g_skelT;
    const int4*   t4   = (const int4*)targ;

    float a0=0.f, a1=0.f, a2=0.f, a3=0.f, a4=0.f, a5=0.f, a6=0.f;

    for (int v = blockIdx.x * RED_THREADS + threadIdx.x; v < NV;
         v += gridDim.x * RED_THREADS) {
        float4 p  = p4[v];
        float4 sp = sp4[v];
        float4 st = st4p[v];
        int4   ti = t4[v];
        float tx = (float)ti.x, ty = (float)ti.y, tz = (float)ti.z, tw = (float)ti.w;

        a0 += sp.x*tx + sp.y*ty + sp.z*tz + sp.w*tw;
        a1 += sp.x + sp.y + sp.z + sp.w;
        a2 += st.x*p.x + st.y*p.y + st.z*p.z + st.w*p.w;
        a3 += st.x + st.y + st.z + st.w;
        a4 += p.x*tx + p.y*ty + p.z*tz + p.w*tw;
        a5 += p.x + p.y + p.z + p.w;
        a6 += tx + ty + tz + tw;
    }

    #pragma unroll
    for (int off = 16; off > 0; off >>= 1) {
        a0 += __shfl_down_sync(0xFFFFFFFF, a0, off);
        a1 += __shfl_down_sync(0xFFFFFFFF, a1, off);
        a2 += __shfl_down_sync(0xFFFFFFFF, a2, off);
        a3 += __shfl_down_sync(0xFFFFFFFF, a3, off);
        a4 += __shfl_down_sync(0xFFFFFFFF, a4, off);
        a5 += __shfl_down_sync(0xFFFFFFFF, a5, off);
        a6 += __shfl_down_sync(0xFFFFFFFF, a6, off);
    }

    __shared__ double sacc[7][RED_THREADS/32];
    int warp = threadIdx.x >> 5, lane = threadIdx.x & 31;
    if (lane == 0) {
        sacc[0][warp]=a0; sacc[1][warp]=a1; sacc[2][warp]=a2;
        sacc[3][warp]=a3; sacc[4][warp]=a4; sacc[5][warp]=a5; sacc[6][warp]=a6;
    }
    __syncthreads();
    if (threadIdx.x < 7) {
        double s = 0.0;
        #pragma unroll
        for (int wv = 0; wv < RED_THREADS/32; wv++) s += sacc[threadIdx.x][wv];
        atomicAdd(&g_sums[threadIdx.x], s);
    }
}

__global__ void finalize_kernel(float* __restrict__ out)
{
    double S_spt=g_sums[0], S_sp=g_sums[1], S_stp=g_sums[2], S_st=g_sums[3];
    double S_pt =g_sums[4], S_p =g_sums[5], S_t =g_sums[6];
    const double SMOOTH = 1.0;
    double tprec = (S_spt + SMOOTH) / (S_sp + SMOOTH);
    double tsens = (S_stp + SMOOTH) / (S_st + SMOOTH);
    double cl    = 2.0 * tprec * tsens / (tprec + tsens + 1e-7);
    double dice  = (2.0 * S_pt + SMOOTH) / (S_p + S_t + SMOOTH);
    out[0] = (float)(1.0 - (0.5 * dice + 0.5 * cl));
}

// ---------------------------------------------------------------------------
// Launch
// ---------------------------------------------------------------------------
extern "C" void kernel_launch(void* const* d_in, const int* in_sizes, int n_in,
                              void* d_out, int out_size)
{
    const float* pred = (const float*)d_in[0];
    const int*   targ = (const int*)d_in[1];
    float* out = (float*)d_out;

    float *prob, *skelP, *skelT, *bufA, *bufB;
    cudaGetSymbolAddress((void**)&prob,  g_prob);
    cudaGetSymbolAddress((void**)&skelP, g_skelP);
    cudaGetSymbolAddress((void**)&skelT, g_skelT);
    cudaGetSymbolAddress((void**)&bufA,  g_bufA);
    cudaGetSymbolAddress((void**)&bufB,  g_bufB);

    dim3 grd(W / TW, H / TH, B);   // 16 x 64 x 8

    zero_sums<<<1, 32>>>();

    // ---- pred skeleton: init + 5 fused double-iterations ----
    init_kernel<true><<<grd, NT>>>(pred, nullptr, prob, skelP);
    {
        const float* in = prob;
        float* ob = bufB;
        for (int i = 0; i < 5; i++) {
            if (i < 4) iter2_kernel<true ><<<grd, NT>>>(in, ob, skelP);
            else       iter2_kernel<false><<<grd, NT>>>(in, ob, skelP);
            in = ob;
            ob = (ob == bufB) ? bufA : bufB;
        }
    }

    // ---- target skeleton ----
    init_kernel<false><<<grd, NT>>>(nullptr, targ, bufA, skelT);
    {
        const float* in = bufA;
        float* ob = bufB;
        for (int i = 0; i < 5; i++) {
            if (i < 4) iter2_kernel<true ><<<grd, NT>>>(in, ob, skelT);
            else       iter2_kernel<false><<<grd, NT>>>(in, ob, skelT);
            in = ob;
            ob = (ob == bufB) ? bufA : bufB;
        }
    }

    reduce_kernel<<<RED_BLOCKS, RED_THREADS>>>(targ);
    finalize_kernel<<<1, 1>>>(out);
}

// round 6
// speedup vs baseline: 3.1512x; 1.1280x over previous
#include <cuda_runtime.h>
#include <math.h>

// Problem constants
#define B  8
#define H  1024
#define W  1024
#define NTOT (B*H*W)

#define NT 256
#define TW 64          // tile width (output)
#define TH 16          // tile height (output)
#define SW 72          // shared row width in floats (64 + 4 halo each side)
#define SH2I 24        // fused-2 iter kernel rows: 16 + 4 halo each side
#define SHN 20         // init kernel rows: 16 + 2 halo each side

#define PINF  __int_as_float(0x7f800000)
#define NINF  __int_as_float(0xff800000)

// ---------------------------------------------------------------------------
// Scratch (allocation-free)
// ---------------------------------------------------------------------------
__device__ float g_prob [NTOT];
__device__ float g_skelP[NTOT];
__device__ float g_skelT[NTOT];
__device__ float g_bufA [NTOT];
__device__ float g_bufB [NTOT];
__device__ double g_sums[7];   // 0:sp*t 1:sp 2:st*p 3:st 4:p*t 5:p 6:t

__global__ void zero_sums() { if (threadIdx.x < 7) g_sums[threadIdx.x] = 0.0; }

// ---------------------------------------------------------------------------
// Helpers
// ---------------------------------------------------------------------------
__device__ __forceinline__ float4 ld4(const float* p) { return *(const float4*)p; }
__device__ __forceinline__ void   st4(float* p, float4 v) { *(float4*)p = v; }

__device__ __forceinline__ float4 min4(float4 a, float4 b) {
    return make_float4(fminf(a.x,b.x), fminf(a.y,b.y), fminf(a.z,b.z), fminf(a.w,b.w));
}

// combine vertical-min v with horizontal-min of center row c (scalars l,r)
__device__ __forceinline__ float4 horiz_min(float4 v, float4 c, float l, float r) {
    float4 m;
    m.x = fminf(v.x, fminf(l,   c.y));
    m.y = fminf(v.y, fminf(c.x, c.z));
    m.z = fminf(v.z, fminf(c.y, c.w));
    m.w = fminf(v.w, fminf(c.z, r  ));
    return m;
}

__device__ __forceinline__ float4 cross_min(float4 u, float4 c, float4 d, float l, float r) {
    return horiz_min(min4(min4(u, d), c), c, l, r);
}

__device__ __forceinline__ float4 row_max3(float4 c, float l, float r) {
    float4 m;
    m.x = fmaxf(l,   fmaxf(c.x, c.y));
    m.y = fmaxf(c.x, fmaxf(c.y, c.z));
    m.z = fmaxf(c.y, fmaxf(c.z, c.w));
    m.w = fmaxf(c.z, fmaxf(c.w, r  ));
    return m;
}

__device__ __forceinline__ float4 max4(float4 a, float4 b) {
    return make_float4(fmaxf(a.x,b.x), fmaxf(a.y,b.y), fmaxf(a.z,b.z), fmaxf(a.w,b.w));
}

// 3x3 dilate at shared offset o
__device__ __forceinline__ float4 dil3x3(const float* s, int o) {
    float4 m0 = row_max3(ld4(&s[o-SW]), s[o-SW-1], s[o-SW+4]);
    float4 m1 = row_max3(ld4(&s[o   ]), s[o   -1], s[o   +4]);
    float4 m2 = row_max3(ld4(&s[o+SW]), s[o+SW-1], s[o+SW+4]);
    return max4(max4(m0, m1), m2);
}

__device__ __forceinline__ void mask_oob(float4& v, int gy, int gx, float pad) {
    if ((unsigned)gy >= H) { v.x = v.y = v.z = v.w = pad; return; }
    if ((unsigned)(gx+0) >= W) v.x = pad;
    if ((unsigned)(gx+1) >= W) v.y = pad;
    if ((unsigned)(gx+2) >= W) v.z = pad;
    if ((unsigned)(gx+3) >= W) v.w = pad;
}

// ---------------------------------------------------------------------------
// INTERIOR fused double iteration (no masking; t1 == e2 == s2):
//   s1 = erode(img); s2 = erode(s1); s3 = erode(s2)
//   skel-update with d1 = dilate(s2) vs s1, then d2 = dilate(s3) vs s2
//   imgOut = s2
// Buffers: sA (img -> s3), sB (s1), sC (s2). Pair-blocked stages (R=2).
// ---------------------------------------------------------------------------
template<bool WRITE_IMG>
__device__ __forceinline__ void iter2_interior(
    const float* __restrict__ img, float* __restrict__ imgOut,
    float* __restrict__ skel, int x0, int y0,
    float* sA, float* sB, float* sC, int tid)
{
    // ---- load img rows 0..23 (12 pairs x 18 cols = 216 jobs)
    if (tid < 216) {
        int p = tid / 18, c4 = (tid % 18) * 4;
        int gy = y0 - 4 + 2*p, gx = x0 - 4 + c4;
        int o = (2*p)*SW + c4;
        st4(&sA[o],      ld4(&img[(size_t)gy * W + gx]));
        st4(&sA[o + SW], ld4(&img[(size_t)(gy+1) * W + gx]));
    }
    __syncthreads();

    // ---- s1 = erode(img): rows 1..22, 11 pairs x 18 = 198 jobs
    if (tid < 198) {
        int p = tid / 18, c4 = (tid % 18) * 4;
        int o = (1 + 2*p)*SW + c4;
        float4 up = ld4(&sA[o - SW]);
        float4 ca = ld4(&sA[o]);
        float4 cb = ld4(&sA[o + SW]);
        float4 dn = ld4(&sA[o + 2*SW]);
        float4 q  = min4(ca, cb);
        float4 ea = horiz_min(min4(up, q), ca, sA[o-1],    sA[o+4]);
        float4 eb = horiz_min(min4(q, dn), cb, sA[o+SW-1], sA[o+SW+4]);
        st4(&sB[o],      ea);
        st4(&sB[o + SW], eb);
    }
    __syncthreads();

    // ---- s2 = erode(s1): rows 2..21, 10 pairs x 18 = 180 jobs
    if (tid < 180) {
        int p = tid / 18, c4 = (tid % 18) * 4;
        int o = (2 + 2*p)*SW + c4;
        float4 up = ld4(&sB[o - SW]);
        float4 ca = ld4(&sB[o]);
        float4 cb = ld4(&sB[o + SW]);
        float4 dn = ld4(&sB[o + 2*SW]);
        float4 q  = min4(ca, cb);
        float4 ea = horiz_min(min4(up, q), ca, sB[o-1],    sB[o+4]);
        float4 eb = horiz_min(min4(q, dn), cb, sB[o+SW-1], sB[o+SW+4]);
        st4(&sC[o],      ea);
        st4(&sC[o + SW], eb);
    }
    __syncthreads();

    // ---- s3 = erode(s2) -> sA: rows 3..20, 9 pairs x 18 = 162 jobs
    if (tid < 162) {
        int p = tid / 18, c4 = (tid % 18) * 4;
        int o = (3 + 2*p)*SW + c4;
        float4 up = ld4(&sC[o - SW]);
        float4 ca = ld4(&sC[o]);
        float4 cb = ld4(&sC[o + SW]);
        float4 dn = ld4(&sC[o + 2*SW]);
        float4 q  = min4(ca, cb);
        float4 ea = horiz_min(min4(up, q), ca, sC[o-1],    sC[o+4]);
        float4 eb = horiz_min(min4(q, dn), cb, sC[o+SW-1], sC[o+SW+4]);
        st4(&sA[o],      ea);
        st4(&sA[o + SW], eb);
    }
    __syncthreads();

    // ---- final: rows 4..19, 8 pairs x 16 cols = 128 jobs
    if (tid < 128) {
        int p = tid >> 4, c4 = ((tid & 15) + 1) * 4;
        int ra = 4 + 2*p;
        int o = ra*SW + c4;

        // d1 over s2 (sC): rows ra-1 .. ra+2
        float4 h0 = row_max3(ld4(&sC[o-SW]),   sC[o-SW-1],   sC[o-SW+4]);
        float4 va = ld4(&sC[o]);
        float4 h1 = row_max3(va,               sC[o-1],      sC[o+4]);
        float4 vb = ld4(&sC[o+SW]);
        float4 h2 = row_max3(vb,               sC[o+SW-1],   sC[o+SW+4]);
        float4 h3 = row_max3(ld4(&sC[o+2*SW]), sC[o+2*SW-1], sC[o+2*SW+4]);
        float4 hq = max4(h1, h2);
        float4 d1a = max4(h0, hq);
        float4 d1b = max4(hq, h3);

        // d2 over s3 (sA)
        float4 g0 = row_max3(ld4(&sA[o-SW]),   sA[o-SW-1],   sA[o-SW+4]);
        float4 g1 = row_max3(ld4(&sA[o]),      sA[o-1],      sA[o+4]);
        float4 g2 = row_max3(ld4(&sA[o+SW]),   sA[o+SW-1],   sA[o+SW+4]);
        float4 g3 = row_max3(ld4(&sA[o+2*SW]), sA[o+2*SW-1], sA[o+2*SW+4]);
        float4 gq = max4(g1, g2);
        float4 d2a = max4(g0, gq);
        float4 d2b = max4(gq, g3);

        // e1 = s1 rows ra, ra+1
        float4 e1a = ld4(&sB[o]);
        float4 e1b = ld4(&sB[o + SW]);

        size_t idx = (size_t)(y0 + ra - 4) * W + (x0 + c4 - 4);

        // row a
        {
            float4 dl1, dl2;
            dl1.x = fmaxf(e1a.x - d1a.x, 0.f); dl1.y = fmaxf(e1a.y - d1a.y, 0.f);
            dl1.z = fmaxf(e1a.z - d1a.z, 0.f); dl1.w = fmaxf(e1a.w - d1a.w, 0.f);
            dl2.x = fmaxf(va.x - d2a.x, 0.f);  dl2.y = fmaxf(va.y - d2a.y, 0.f);
            dl2.z = fmaxf(va.z - d2a.z, 0.f);  dl2.w = fmaxf(va.w - d2a.w, 0.f);
            float4 s = ld4(&skel[idx]);
            s.x += fmaxf(dl1.x - s.x*dl1.x, 0.f);
            s.y += fmaxf(dl1.y - s.y*dl1.y, 0.f);
            s.z += fmaxf(dl1.z - s.z*dl1.z, 0.f);
            s.w += fmaxf(dl1.w - s.w*dl1.w, 0.f);
            s.x += fmaxf(dl2.x - s.x*dl2.x, 0.f);
            s.y += fmaxf(dl2.y - s.y*dl2.y, 0.f);
            s.z += fmaxf(dl2.z - s.z*dl2.z, 0.f);
            s.w += fmaxf(dl2.w - s.w*dl2.w, 0.f);
            if (WRITE_IMG) st4(&imgOut[idx], va);
            st4(&skel[idx], s);
        }
        // row b
        {
            float4 dl1, dl2;
            dl1.x = fmaxf(e1b.x - d1b.x, 0.f); dl1.y = fmaxf(e1b.y - d1b.y, 0.f);
            dl1.z = fmaxf(e1b.z - d1b.z, 0.f); dl1.w = fmaxf(e1b.w - d1b.w, 0.f);
            dl2.x = fmaxf(vb.x - d2b.x, 0.f);  dl2.y = fmaxf(vb.y - d2b.y, 0.f);
            dl2.z = fmaxf(vb.z - d2b.z, 0.f);  dl2.w = fmaxf(vb.w - d2b.w, 0.f);
            float4 s = ld4(&skel[idx + W]);
            s.x += fmaxf(dl1.x - s.x*dl1.x, 0.f);
            s.y += fmaxf(dl1.y - s.y*dl1.y, 0.f);
            s.z += fmaxf(dl1.z - s.z*dl1.z, 0.f);
            s.w += fmaxf(dl1.w - s.w*dl1.w, 0.f);
            s.x += fmaxf(dl2.x - s.x*dl2.x, 0.f);
            s.y += fmaxf(dl2.y - s.y*dl2.y, 0.f);
            s.z += fmaxf(dl2.z - s.z*dl2.z, 0.f);
            s.w += fmaxf(dl2.w - s.w*dl2.w, 0.f);
            if (WRITE_IMG) st4(&imgOut[idx + W], vb);
            st4(&skel[idx + W], s);
        }
    }
}

// ---------------------------------------------------------------------------
// BORDER fused double iteration (exact R4 masked path)
// ---------------------------------------------------------------------------
template<bool WRITE_IMG>
__device__ __forceinline__ void iter2_border(
    const float* __restrict__ img, float* __restrict__ imgOut,
    float* __restrict__ skel, int x0, int y0,
    float* sImg, float* sE1, float* sT1, float* sT2, int tid)
{
    for (int i = tid; i < SH2I*18; i += NT) {
        int r = i / 18, c4 = (i - r*18) * 4;
        int gy = y0 - 4 + r, gx = x0 - 4 + c4;
        float4 v = make_float4(PINF, PINF, PINF, PINF);
        if ((unsigned)gy < H) {
            const float* row = &img[gy*W];
            if ((unsigned)(gx+0) < W) v.x = row[gx+0];
            if ((unsigned)(gx+1) < W) v.y = row[gx+1];
            if ((unsigned)(gx+2) < W) v.z = row[gx+2];
            if ((unsigned)(gx+3) < W) v.w = row[gx+3];
        }
        st4(&sImg[r*SW + c4], v);
    }
    __syncthreads();

    for (int i = tid; i < 22*18; i += NT) {
        int r = 1 + i / 18, c4 = (i % 18) * 4;
        int o = r*SW + c4;
        float4 e = cross_min(ld4(&sImg[o-SW]), ld4(&sImg[o]), ld4(&sImg[o+SW]),
                             sImg[o-1], sImg[o+4]);
        mask_oob(e, y0-4+r, x0-4+c4, PINF);
        st4(&sE1[o], e);
    }
    __syncthreads();

    for (int i = tid; i < 20*18; i += NT) {
        int r = 2 + i / 18, c4 = (i % 18) * 4;
        int o = r*SW + c4;
        float4 t = cross_min(ld4(&sE1[o-SW]), ld4(&sE1[o]), ld4(&sE1[o+SW]),
                             sE1[o-1], sE1[o+4]);
        float4 e2 = t;
        mask_oob(t,  y0-4+r, x0-4+c4, NINF);
        mask_oob(e2, y0-4+r, x0-4+c4, PINF);
        st4(&sT1[o], t);
        st4(&sImg[o], e2);
    }
    __syncthreads();

    for (int i = tid; i < 18*18; i += NT) {
        int r = 3 + i / 18, c4 = (i % 18) * 4;
        int o = r*SW + c4;
        float4 t = cross_min(ld4(&sImg[o-SW]), ld4(&sImg[o]), ld4(&sImg[o+SW]),
                             sImg[o-1], sImg[o+4]);
        mask_oob(t, y0-4+r, x0-4+c4, NINF);
        st4(&sT2[o], t);
    }
    __syncthreads();

    {
        int r  = 4 + (tid >> 4);
        int c4 = ((tid & 15) + 1) * 4;
        int o  = r*SW + c4;

        float4 d1 = dil3x3(sT1, o);
        float4 d2 = dil3x3(sT2, o);
        float4 e1 = ld4(&sE1[o]);
        float4 e2 = ld4(&sImg[o]);

        float4 dl1, dl2;
        dl1.x = fmaxf(e1.x - d1.x, 0.f); dl1.y = fmaxf(e1.y - d1.y, 0.f);
        dl1.z = fmaxf(e1.z - d1.z, 0.f); dl1.w = fmaxf(e1.w - d1.w, 0.f);
        dl2.x = fmaxf(e2.x - d2.x, 0.f); dl2.y = fmaxf(e2.y - d2.y, 0.f);
        dl2.z = fmaxf(e2.z - d2.z, 0.f); dl2.w = fmaxf(e2.w - d2.w, 0.f);

        size_t idx = (size_t)(y0 + r - 4) * W + (x0 + c4 - 4);
        float4 s = ld4(&skel[idx]);
        s.x += fmaxf(dl1.x - s.x * dl1.x, 0.f);
        s.y += fmaxf(dl1.y - s.y * dl1.y, 0.f);
        s.z += fmaxf(dl1.z - s.z * dl1.z, 0.f);
        s.w += fmaxf(dl1.w - s.w * dl1.w, 0.f);
        s.x += fmaxf(dl2.x - s.x * dl2.x, 0.f);
        s.y += fmaxf(dl2.y - s.y * dl2.y, 0.f);
        s.z += fmaxf(dl2.z - s.z * dl2.z, 0.f);
        s.w += fmaxf(dl2.w - s.w * dl2.w, 0.f);

        if (WRITE_IMG) st4(&imgOut[idx], e2);
        st4(&skel[idx], s);
    }
}

template<bool WRITE_IMG>
__global__ __launch_bounds__(NT, 6)
void iter2_kernel(const float* __restrict__ imgIn, float* __restrict__ imgOut,
                  float* __restrict__ skel)
{
    __shared__ float sA[SH2I*SW];
    __shared__ float sB[SH2I*SW];
    __shared__ float sC[SH2I*SW];
    __shared__ float sD[SH2I*SW];
    int x0 = blockIdx.x * TW, y0 = blockIdx.y * TH;
    size_t off = (size_t)blockIdx.z * H * W;
    int tid = threadIdx.x;
    bool border = (blockIdx.x == 0) | (blockIdx.x == gridDim.x-1) |
                  (blockIdx.y == 0) | (blockIdx.y == gridDim.y-1);
    if (border) iter2_border<WRITE_IMG>(imgIn+off, imgOut+off, skel+off, x0, y0, sA, sB, sC, sD, tid);
    else        iter2_interior<WRITE_IMG>(imgIn+off, imgOut+off, skel+off, x0, y0, sA, sB, sC, tid);
}

// ---------------------------------------------------------------------------
// Init: base = sigmoid(pred) | float(target)
// ---------------------------------------------------------------------------
template<bool IS_PRED, bool BORDER>
__device__ __forceinline__ void init_impl(
    const float* __restrict__ pred, const int* __restrict__ targ,
    float* __restrict__ baseOut, float* __restrict__ skelOut,
    int x0, int y0, float* s0, float* s1, int tid)
{
    for (int i = tid; i < SHN*18; i += NT) {
        int r = i / 18, c4 = (i - r*18) * 4;
        int gy = y0 - 2 + r, gx = x0 - 4 + c4;
        float4 v;
        if (!BORDER) {
            if (IS_PRED) {
                float4 x = ld4(&pred[gy*W + gx]);
                v.x = 1.f / (1.f + __expf(-x.x));
                v.y = 1.f / (1.f + __expf(-x.y));
                v.z = 1.f / (1.f + __expf(-x.z));
                v.w = 1.f / (1.f + __expf(-x.w));
            } else {
                int4 t = *(const int4*)&targ[gy*W + gx];
                v = make_float4((float)t.x, (float)t.y, (float)t.z, (float)t.w);
            }
        } else {
            v = make_float4(PINF, PINF, PINF, PINF);
            if ((unsigned)gy < H) {
                #pragma unroll
                for (int k = 0; k < 4; k++) {
                    float* vk = k==0 ? &v.x : k==1 ? &v.y : k==2 ? &v.z : &v.w;
                    if ((unsigned)(gx+k) < W) {
                        if (IS_PRED) { float x = pred[gy*W + gx + k]; *vk = 1.f/(1.f+__expf(-x)); }
                        else         { *vk = (float)targ[gy*W + gx + k]; }
                    }
                }
            }
        }
        st4(&s0[r*SW + c4], v);
    }
    __syncthreads();

    for (int i = tid; i < 18*18; i += NT) {
        int r = 1 + i / 18, c4 = (i % 18) * 4;
        int o = r*SW + c4;
        float4 e = cross_min(ld4(&s0[o-SW]), ld4(&s0[o]), ld4(&s0[o+SW]),
                             s0[o-1], s0[o+4]);
        if (BORDER) mask_oob(e, y0-2+r, x0-4+c4, NINF);
        st4(&s1[o], e);
    }
    __syncthreads();

    {
        int r  = 2 + (tid >> 4);
        int c4 = ((tid & 15) + 1) * 4;
        int o  = r*SW + c4;
        float4 d = dil3x3(s1, o);
        float4 base = ld4(&s0[o]);
        float4 sk;
        sk.x = fmaxf(base.x - d.x, 0.f);
        sk.y = fmaxf(base.y - d.y, 0.f);
        sk.z = fmaxf(base.z - d.z, 0.f);
        sk.w = fmaxf(base.w - d.w, 0.f);
        size_t idx = (size_t)(y0 + r - 2) * W + (x0 + c4 - 4);
        st4(&baseOut[idx], base);
        st4(&skelOut[idx], sk);
    }
}

template<bool IS_PRED>
__global__ __launch_bounds__(NT)
void init_kernel(const float* __restrict__ pred, const int* __restrict__ targ,
                 float* __restrict__ baseOut, float* __restrict__ skelOut)
{
    __shared__ float s0[SHN*SW];
    __shared__ float s1[SHN*SW];
    int x0 = blockIdx.x * TW, y0 = blockIdx.y * TH;
    size_t off = (size_t)blockIdx.z * H * W;
    int tid = threadIdx.x;
    const float* p = IS_PRED ? pred + off : nullptr;
    const int*   t = IS_PRED ? nullptr : targ + off;
    bool border = (blockIdx.x == 0) | (blockIdx.x == gridDim.x-1) |
                  (blockIdx.y == 0) | (blockIdx.y == gridDim.y-1);
    if (border) init_impl<IS_PRED, true >(p, t, baseOut+off, skelOut+off, x0, y0, s0, s1, tid);
    else        init_impl<IS_PRED, false>(p, t, baseOut+off, skelOut+off, x0, y0, s0, s1, tid);
}

// ---------------------------------------------------------------------------
// Reduction: 7 sums over 8M elements
// ---------------------------------------------------------------------------
#define RED_BLOCKS 2048
#define RED_THREADS 256

__global__ __launch_bounds__(RED_THREADS)
void reduce_kernel(const int* __restrict__ targ)
{
    const int NV = NTOT / 4;
    const float4* p4   = (const float4*)g_prob;
    const float4* sp4  = (const float4*)g_skelP;
    const float4* st4p = (const float4*)g_skelT;
    const int4*   t4   = (const int4*)targ;

    float a0=0.f, a1=0.f, a2=0.f, a3=0.f, a4=0.f, a5=0.f, a6=0.f;

    for (int v = blockIdx.x * RED_THREADS + threadIdx.x; v < NV;
         v += gridDim.x * RED_THREADS) {
        float4 p  = p4[v];
        float4 sp = sp4[v];
        float4 st = st4p[v];
        int4   ti = t4[v];
        float tx = (float)ti.x, ty = (float)ti.y, tz = (float)ti.z, tw = (float)ti.w;

        a0 += sp.x*tx + sp.y*ty + sp.z*tz + sp.w*tw;
        a1 += sp.x + sp.y + sp.z + sp.w;
        a2 += st.x*p.x + st.y*p.y + st.z*p.z + st.w*p.w;
        a3 += st.x + st.y + st.z + st.w;
        a4 += p.x*tx + p.y*ty + p.z*tz + p.w*tw;
        a5 += p.x + p.y + p.z + p.w;
        a6 += tx + ty + tz + tw;
    }

    #pragma unroll
    for (int off = 16; off > 0; off >>= 1) {
        a0 += __shfl_down_sync(0xFFFFFFFF, a0, off);
        a1 += __shfl_down_sync(0xFFFFFFFF, a1, off);
        a2 += __shfl_down_sync(0xFFFFFFFF, a2, off);
        a3 += __shfl_down_sync(0xFFFFFFFF, a3, off);
        a4 += __shfl_down_sync(0xFFFFFFFF, a4, off);
        a5 += __shfl_down_sync(0xFFFFFFFF, a5, off);
        a6 += __shfl_down_sync(0xFFFFFFFF, a6, off);
    }

    __shared__ double sacc[7][RED_THREADS/32];
    int warp = threadIdx.x >> 5, lane = threadIdx.x & 31;
    if (lane == 0) {
        sacc[0][warp]=a0; sacc[1][warp]=a1; sacc[2][warp]=a2;
        sacc[3][warp]=a3; sacc[4][warp]=a4; sacc[5][warp]=a5; sacc[6][warp]=a6;
    }
    __syncthreads();
    if (threadIdx.x < 7) {
        double s = 0.0;
        #pragma unroll
        for (int wv = 0; wv < RED_THREADS/32; wv++) s += sacc[threadIdx.x][wv];
        atomicAdd(&g_sums[threadIdx.x], s);
    }
}

__global__ void finalize_kernel(float* __restrict__ out)
{
    double S_spt=g_sums[0], S_sp=g_sums[1], S_stp=g_sums[2], S_st=g_sums[3];
    double S_pt =g_sums[4], S_p =g_sums[5], S_t =g_sums[6];
    const double SMOOTH = 1.0;
    double tprec = (S_spt + SMOOTH) / (S_sp + SMOOTH);
    double tsens = (S_stp + SMOOTH) / (S_st + SMOOTH);
    double cl    = 2.0 * tprec * tsens / (tprec + tsens + 1e-7);
    double dice  = (2.0 * S_pt + SMOOTH) / (S_p + S_t + SMOOTH);
    out[0] = (float)(1.0 - (0.5 * dice + 0.5 * cl));
}

// ---------------------------------------------------------------------------
// Launch
// ---------------------------------------------------------------------------
extern "C" void kernel_launch(void* const* d_in, const int* in_sizes, int n_in,
                              void* d_out, int out_size)
{
    const float* pred = (const float*)d_in[0];
    const int*   targ = (const int*)d_in[1];
    float* out = (float*)d_out;

    float *prob, *skelP, *skelT, *bufA, *bufB;
    cudaGetSymbolAddress((void**)&prob,  g_prob);
    cudaGetSymbolAddress((void**)&skelP, g_skelP);
    cudaGetSymbolAddress((void**)&skelT, g_skelT);
    cudaGetSymbolAddress((void**)&bufA,  g_bufA);
    cudaGetSymbolAddress((void**)&bufB,  g_bufB);

    dim3 grd(W / TW, H / TH, B);   // 16 x 64 x 8

    zero_sums<<<1, 32>>>();

    // ---- pred skeleton: init + 5 fused double-iterations ----
    init_kernel<true><<<grd, NT>>>(pred, nullptr, prob, skelP);
    {
        const float* in = prob;
        float* ob = bufB;
        for (int i = 0; i < 5; i++) {
            if (i < 4) iter2_kernel<true ><<<grd, NT>>>(in, ob, skelP);
            else       iter2_kernel<false><<<grd, NT>>>(in, ob, skelP);
            in = ob;
            ob = (ob == bufB) ? bufA : bufB;
        }
    }

    // ---- target skeleton ----
    init_kernel<false><<<grd, NT>>>(nullptr, targ, bufA, skelT);
    {
        const float* in = bufA;
        float* ob = bufB;
        for (int i = 0; i < 5; i++) {
            if (i < 4) iter2_kernel<true ><<<grd, NT>>>(in, ob, skelT);
            else       iter2_kernel<false><<<grd, NT>>>(in, ob, skelT);
            in = ob;
            ob = (ob == bufB) ? bufA : bufB;
        }
    }

    reduce_kernel<<<RED_BLOCKS, RED_THREADS>>>(targ);
    finalize_kernel<<<1, 1>>>(out);
}

// round 7
// speedup vs baseline: 3.2415x; 1.0287x over previous
#include <cuda_runtime.h>
#include <math.h>

// Problem constants
#define B  8
#define H  1024
#define W  1024
#define NTOT (B*H*W)

#define NT 256
#define TW 64          // tile width (output)
#define TH 16          // tile height (output)
#define SW 72          // shared row width in floats (64 + 4 halo each side)
#define SH2I 24        // fused-2 iter kernel rows: 16 + 4 halo each side
#define SHN 20         // init kernel rows: 16 + 2 halo each side

#define PINF  __int_as_float(0x7f800000)
#define NINF  __int_as_float(0xff800000)

// ---------------------------------------------------------------------------
// Scratch (allocation-free)
// ---------------------------------------------------------------------------
__device__ float g_prob [NTOT];
__device__ float g_skelP[NTOT];
__device__ float g_skelT[NTOT];
__device__ float g_bufA [NTOT];
__device__ float g_bufB [NTOT];
__device__ double g_sums[7];   // 0:sp*t 1:sp 2:st*p 3:st 4:p*t 5:p 6:t

__global__ void zero_sums() { if (threadIdx.x < 7) g_sums[threadIdx.x] = 0.0; }

// ---------------------------------------------------------------------------
// Helpers
// ---------------------------------------------------------------------------
__device__ __forceinline__ float4 ld4(const float* p) { return *(const float4*)p; }
__device__ __forceinline__ void   st4(float* p, float4 v) { *(float4*)p = v; }

__device__ __forceinline__ float4 min4(float4 a, float4 b) {
    return make_float4(fminf(a.x,b.x), fminf(a.y,b.y), fminf(a.z,b.z), fminf(a.w,b.w));
}

__device__ __forceinline__ float4 horiz_min(float4 v, float4 c, float l, float r) {
    float4 m;
    m.x = fminf(v.x, fminf(l,   c.y));
    m.y = fminf(v.y, fminf(c.x, c.z));
    m.z = fminf(v.z, fminf(c.y, c.w));
    m.w = fminf(v.w, fminf(c.z, r  ));
    return m;
}

__device__ __forceinline__ float4 cross_min(float4 u, float4 c, float4 d, float l, float r) {
    return horiz_min(min4(min4(u, d), c), c, l, r);
}

__device__ __forceinline__ float4 row_max3(float4 c, float l, float r) {
    float4 m;
    m.x = fmaxf(l,   fmaxf(c.x, c.y));
    m.y = fmaxf(c.x, fmaxf(c.y, c.z));
    m.z = fmaxf(c.y, fmaxf(c.z, c.w));
    m.w = fmaxf(c.z, fmaxf(c.w, r  ));
    return m;
}

__device__ __forceinline__ float4 max4(float4 a, float4 b) {
    return make_float4(fmaxf(a.x,b.x), fmaxf(a.y,b.y), fmaxf(a.z,b.z), fmaxf(a.w,b.w));
}

__device__ __forceinline__ float4 dil3x3(const float* s, int o) {
    float4 m0 = row_max3(ld4(&s[o-SW]), s[o-SW-1], s[o-SW+4]);
    float4 m1 = row_max3(ld4(&s[o   ]), s[o   -1], s[o   +4]);
    float4 m2 = row_max3(ld4(&s[o+SW]), s[o+SW-1], s[o+SW+4]);
    return max4(max4(m0, m1), m2);
}

__device__ __forceinline__ void mask_oob(float4& v, int gy, int gx, float pad) {
    if ((unsigned)gy >= H) { v.x = v.y = v.z = v.w = pad; return; }
    if ((unsigned)(gx+0) >= W) v.x = pad;
    if ((unsigned)(gx+1) >= W) v.y = pad;
    if ((unsigned)(gx+2) >= W) v.z = pad;
    if ((unsigned)(gx+3) >= W) v.w = pad;
}

__device__ __forceinline__ void skel_update(float4& s, float4 e, float4 d) {
    float4 dl;
    dl.x = fmaxf(e.x - d.x, 0.f);
    dl.y = fmaxf(e.y - d.y, 0.f);
    dl.z = fmaxf(e.z - d.z, 0.f);
    dl.w = fmaxf(e.w - d.w, 0.f);
    s.x += fmaxf(dl.x - s.x*dl.x, 0.f);
    s.y += fmaxf(dl.y - s.y*dl.y, 0.f);
    s.z += fmaxf(dl.z - s.z*dl.z, 0.f);
    s.w += fmaxf(dl.w - s.w*dl.w, 0.f);
}

// ---------------------------------------------------------------------------
// INTERIOR fused double iteration (no masking; t1 == e2 == s2):
//   s1 = erode(img); s2 = erode(s1); s3 = erode(s2)
//   skel-update with d1 = dilate(s2) vs s1, then d2 = dilate(s3) vs s2
//   imgOut = s2
// Buffers: sA (img -> s3), sB (s1), sC (s2). Pair-blocked stages (R=2).
// ---------------------------------------------------------------------------
template<bool WRITE_IMG>
__device__ __forceinline__ void iter2_interior(
    const float* __restrict__ img, float* __restrict__ imgOut,
    float* __restrict__ skel, int x0, int y0,
    float* sA, float* sB, float* sC, int tid)
{
    // ---- load img rows 0..23 (12 pairs x 18 cols = 216 jobs)
    if (tid < 216) {
        int p = tid / 18, c4 = (tid % 18) * 4;
        int gy = y0 - 4 + 2*p, gx = x0 - 4 + c4;
        int o = (2*p)*SW + c4;
        st4(&sA[o],      ld4(&img[(size_t)gy * W + gx]));
        st4(&sA[o + SW], ld4(&img[(size_t)(gy+1) * W + gx]));
    }
    __syncthreads();

    // ---- s1 = erode(img): rows 1..22, 11 pairs x 18 = 198 jobs
    if (tid < 198) {
        int p = tid / 18, c4 = (tid % 18) * 4;
        int o = (1 + 2*p)*SW + c4;
        float4 up = ld4(&sA[o - SW]);
        float4 ca = ld4(&sA[o]);
        float4 cb = ld4(&sA[o + SW]);
        float4 dn = ld4(&sA[o + 2*SW]);
        float4 q  = min4(ca, cb);
        float4 ea = horiz_min(min4(up, q), ca, sA[o-1],    sA[o+4]);
        float4 eb = horiz_min(min4(q, dn), cb, sA[o+SW-1], sA[o+SW+4]);
        st4(&sB[o],      ea);
        st4(&sB[o + SW], eb);
    }
    __syncthreads();

    // ---- s2 = erode(s1): rows 2..21, 10 pairs x 18 = 180 jobs
    if (tid < 180) {
        int p = tid / 18, c4 = (tid % 18) * 4;
        int o = (2 + 2*p)*SW + c4;
        float4 up = ld4(&sB[o - SW]);
        float4 ca = ld4(&sB[o]);
        float4 cb = ld4(&sB[o + SW]);
        float4 dn = ld4(&sB[o + 2*SW]);
        float4 q  = min4(ca, cb);
        float4 ea = horiz_min(min4(up, q), ca, sB[o-1],    sB[o+4]);
        float4 eb = horiz_min(min4(q, dn), cb, sB[o+SW-1], sB[o+SW+4]);
        st4(&sC[o],      ea);
        st4(&sC[o + SW], eb);
    }
    __syncthreads();

    // ---- s3 = erode(s2) -> sA: rows 3..20, 9 pairs x 18 = 162 jobs
    if (tid < 162) {
        int p = tid / 18, c4 = (tid % 18) * 4;
        int o = (3 + 2*p)*SW + c4;
        float4 up = ld4(&sC[o - SW]);
        float4 ca = ld4(&sC[o]);
        float4 cb = ld4(&sC[o + SW]);
        float4 dn = ld4(&sC[o + 2*SW]);
        float4 q  = min4(ca, cb);
        float4 ea = horiz_min(min4(up, q), ca, sC[o-1],    sC[o+4]);
        float4 eb = horiz_min(min4(q, dn), cb, sC[o+SW-1], sC[o+SW+4]);
        st4(&sA[o],      ea);
        st4(&sA[o + SW], eb);
    }
    __syncthreads();

    // ---- final: rows 4..19, 8 pairs x 16 cols = 128 jobs
    if (tid < 128) {
        int p = tid >> 4, c4 = ((tid & 15) + 1) * 4;
        int ra = 4 + 2*p;
        int o = ra*SW + c4;

        // d1 over s2 (sC): rows ra-1 .. ra+2
        float4 h0 = row_max3(ld4(&sC[o-SW]),   sC[o-SW-1],   sC[o-SW+4]);
        float4 va = ld4(&sC[o]);
        float4 h1 = row_max3(va,               sC[o-1],      sC[o+4]);
        float4 vb = ld4(&sC[o+SW]);
        float4 h2 = row_max3(vb,               sC[o+SW-1],   sC[o+SW+4]);
        float4 h3 = row_max3(ld4(&sC[o+2*SW]), sC[o+2*SW-1], sC[o+2*SW+4]);
        float4 hq = max4(h1, h2);
        float4 d1a = max4(h0, hq);
        float4 d1b = max4(hq, h3);

        // d2 over s3 (sA)
        float4 g0 = row_max3(ld4(&sA[o-SW]),   sA[o-SW-1],   sA[o-SW+4]);
        float4 g1 = row_max3(ld4(&sA[o]),      sA[o-1],      sA[o+4]);
        float4 g2 = row_max3(ld4(&sA[o+SW]),   sA[o+SW-1],   sA[o+SW+4]);
        float4 g3 = row_max3(ld4(&sA[o+2*SW]), sA[o+2*SW-1], sA[o+2*SW+4]);
        float4 gq = max4(g1, g2);
        float4 d2a = max4(g0, gq);
        float4 d2b = max4(gq, g3);

        float4 e1a = ld4(&sB[o]);
        float4 e1b = ld4(&sB[o + SW]);

        size_t idx = (size_t)(y0 + ra - 4) * W + (x0 + c4 - 4);

        float4 s = ld4(&skel[idx]);
        skel_update(s, e1a, d1a);
        skel_update(s, va,  d2a);
        if (WRITE_IMG) st4(&imgOut[idx], va);
        st4(&skel[idx], s);

        float4 s2 = ld4(&skel[idx + W]);
        skel_update(s2, e1b, d1b);
        skel_update(s2, vb,  d2b);
        if (WRITE_IMG) st4(&imgOut[idx + W], vb);
        st4(&skel[idx + W], s2);
    }
}

// ---------------------------------------------------------------------------
// BORDER fused double iteration, 3-buffer variant.
//   sA: img -> t1 -> t2       sB: e1       sC: e2
//   Final split in two phases so t2 can reuse sA after d1 is consumed.
// ---------------------------------------------------------------------------
template<bool WRITE_IMG>
__device__ __forceinline__ void iter2_border(
    const float* __restrict__ img, float* __restrict__ imgOut,
    float* __restrict__ skel, int x0, int y0,
    float* sA, float* sB, float* sC, int tid)
{
    // load img rows 0..23, OOB +inf
    for (int i = tid; i < SH2I*18; i += NT) {
        int r = i / 18, c4 = (i - r*18) * 4;
        int gy = y0 - 4 + r, gx = x0 - 4 + c4;
        float4 v = make_float4(PINF, PINF, PINF, PINF);
        if ((unsigned)gy < H) {
            const float* row = &img[gy*W];
            if ((unsigned)(gx+0) < W) v.x = row[gx+0];
            if ((unsigned)(gx+1) < W) v.y = row[gx+1];
            if ((unsigned)(gx+2) < W) v.z = row[gx+2];
            if ((unsigned)(gx+3) < W) v.w = row[gx+3];
        }
        st4(&sA[r*SW + c4], v);
    }
    __syncthreads();

    // e1 = erode(img), rows 1..22, masked +inf
    for (int i = tid; i < 22*18; i += NT) {
        int r = 1 + i / 18, c4 = (i % 18) * 4;
        int o = r*SW + c4;
        float4 e = cross_min(ld4(&sA[o-SW]), ld4(&sA[o]), ld4(&sA[o+SW]),
                             sA[o-1], sA[o+4]);
        mask_oob(e, y0-4+r, x0-4+c4, PINF);
        st4(&sB[o], e);
    }
    __syncthreads();

    // t1 = erode(e1) masked -inf -> sA (img dead); e2 = same masked +inf -> sC
    for (int i = tid; i < 20*18; i += NT) {
        int r = 2 + i / 18, c4 = (i % 18) * 4;
        int o = r*SW + c4;
        float4 t = cross_min(ld4(&sB[o-SW]), ld4(&sB[o]), ld4(&sB[o+SW]),
                             sB[o-1], sB[o+4]);
        float4 e2 = t;
        mask_oob(t,  y0-4+r, x0-4+c4, NINF);
        mask_oob(e2, y0-4+r, x0-4+c4, PINF);
        st4(&sA[o], t);
        st4(&sC[o], e2);
    }
    __syncthreads();

    // Phase 1 of final: d1 from t1 (sA), delta1 into register skel
    int r  = 4 + (tid >> 4);
    int c4 = ((tid & 15) + 1) * 4;
    int o  = r*SW + c4;
    size_t idx = (size_t)(y0 + r - 4) * W + (x0 + c4 - 4);
    float4 s;
    if (tid < 128) {
        float4 d1 = dil3x3(sA, o);
        float4 e1 = ld4(&sB[o]);
        s = ld4(&skel[idx]);
        skel_update(s, e1, d1);
    }
    __syncthreads();

    // t2 = erode(e2) masked -inf -> sA (t1 dead), rows 3..20
    for (int i = tid; i < 18*18; i += NT) {
        int rr = 3 + i / 18, cc = (i % 18) * 4;
        int oo = rr*SW + cc;
        float4 t = cross_min(ld4(&sC[oo-SW]), ld4(&sC[oo]), ld4(&sC[oo+SW]),
                             sC[oo-1], sC[oo+4]);
        mask_oob(t, y0-4+rr, x0-4+cc, NINF);
        st4(&sA[oo], t);
    }
    __syncthreads();

    // Phase 2 of final: d2 from t2 (sA), delta2, store
    if (tid < 128) {
        float4 d2 = dil3x3(sA, o);
        float4 e2 = ld4(&sC[o]);
        skel_update(s, e2, d2);
        if (WRITE_IMG) st4(&imgOut[idx], e2);
        st4(&skel[idx], s);
    }
}

template<bool WRITE_IMG>
__global__ __launch_bounds__(NT)
void iter2_kernel(const float* __restrict__ imgIn, float* __restrict__ imgOut,
                  float* __restrict__ skel)
{
    __shared__ float sA[SH2I*SW];
    __shared__ float sB[SH2I*SW];
    __shared__ float sC[SH2I*SW];
    int x0 = blockIdx.x * TW, y0 = blockIdx.y * TH;
    size_t off = (size_t)blockIdx.z * H * W;
    int tid = threadIdx.x;
    bool border = (blockIdx.x == 0) | (blockIdx.x == gridDim.x-1) |
                  (blockIdx.y == 0) | (blockIdx.y == gridDim.y-1);
    if (border) iter2_border<WRITE_IMG>(imgIn+off, imgOut+off, skel+off, x0, y0, sA, sB, sC, tid);
    else        iter2_interior<WRITE_IMG>(imgIn+off, imgOut+off, skel+off, x0, y0, sA, sB, sC, tid);
}

// ---------------------------------------------------------------------------
// Init: base = sigmoid(pred) | float(target)
// ---------------------------------------------------------------------------
template<bool IS_PRED, bool BORDER>
__device__ __forceinline__ void init_impl(
    const float* __restrict__ pred, const int* __restrict__ targ,
    float* __restrict__ baseOut, float* __restrict__ skelOut,
    int x0, int y0, float* s0, float* s1, int tid)
{
    for (int i = tid; i < SHN*18; i += NT) {
        int r = i / 18, c4 = (i - r*18) * 4;
        int gy = y0 - 2 + r, gx = x0 - 4 + c4;
        float4 v;
        if (!BORDER) {
            if (IS_PRED) {
                float4 x = ld4(&pred[gy*W + gx]);
                v.x = 1.f / (1.f + __expf(-x.x));
                v.y = 1.f / (1.f + __expf(-x.y));
                v.z = 1.f / (1.f + __expf(-x.z));
                v.w = 1.f / (1.f + __expf(-x.w));
            } else {
                int4 t = *(const int4*)&targ[gy*W + gx];
                v = make_float4((float)t.x, (float)t.y, (float)t.z, (float)t.w);
            }
        } else {
            v = make_float4(PINF, PINF, PINF, PINF);
            if ((unsigned)gy < H) {
                #pragma unroll
                for (int k = 0; k < 4; k++) {
                    float* vk = k==0 ? &v.x : k==1 ? &v.y : k==2 ? &v.z : &v.w;
                    if ((unsigned)(gx+k) < W) {
                        if (IS_PRED) { float x = pred[gy*W + gx + k]; *vk = 1.f/(1.f+__expf(-x)); }
                        else         { *vk = (float)targ[gy*W + gx + k]; }
                    }
                }
            }
        }
        st4(&s0[r*SW + c4], v);
    }
    __syncthreads();

    for (int i = tid; i < 18*18; i += NT) {
        int r = 1 + i / 18, c4 = (i % 18) * 4;
        int o = r*SW + c4;
        float4 e = cross_min(ld4(&s0[o-SW]), ld4(&s0[o]), ld4(&s0[o+SW]),
                             s0[o-1], s0[o+4]);
        if (BORDER) mask_oob(e, y0-2+r, x0-4+c4, NINF);
        st4(&s1[o], e);
    }
    __syncthreads();

    {
        int r  = 2 + (tid >> 4);
        int c4 = ((tid & 15) + 1) * 4;
        int o  = r*SW + c4;
        float4 d = dil3x3(s1, o);
        float4 base = ld4(&s0[o]);
        float4 sk;
        sk.x = fmaxf(base.x - d.x, 0.f);
        sk.y = fmaxf(base.y - d.y, 0.f);
        sk.z = fmaxf(base.z - d.z, 0.f);
        sk.w = fmaxf(base.w - d.w, 0.f);
        size_t idx = (size_t)(y0 + r - 2) * W + (x0 + c4 - 4);
        st4(&baseOut[idx], base);
        st4(&skelOut[idx], sk);
    }
}

template<bool IS_PRED>
__global__ __launch_bounds__(NT)
void init_kernel(const float* __restrict__ pred, const int* __restrict__ targ,
                 float* __restrict__ baseOut, float* __restrict__ skelOut)
{
    __shared__ float s0[SHN*SW];
    __shared__ float s1[SHN*SW];
    int x0 = blockIdx.x * TW, y0 = blockIdx.y * TH;
    size_t off = (size_t)blockIdx.z * H * W;
    int tid = threadIdx.x;
    const float* p = IS_PRED ? pred + off : nullptr;
    const int*   t = IS_PRED ? nullptr : targ + off;
    bool border = (blockIdx.x == 0) | (blockIdx.x == gridDim.x-1) |
                  (blockIdx.y == 0) | (blockIdx.y == gridDim.y-1);
    if (border) init_impl<IS_PRED, true >(p, t, baseOut+off, skelOut+off, x0, y0, s0, s1, tid);
    else        init_impl<IS_PRED, false>(p, t, baseOut+off, skelOut+off, x0, y0, s0, s1, tid);
}

// ---------------------------------------------------------------------------
// Reduction: 7 sums over 8M elements
// ---------------------------------------------------------------------------
#define RED_BLOCKS 2048
#define RED_THREADS 256

__global__ __launch_bounds__(RED_THREADS)
void reduce_kernel(const int* __restrict__ targ)
{
    const int NV = NTOT / 4;
    const float4* p4   = (const float4*)g_prob;
    const float4* sp4  = (const float4*)g_skelP;
    const float4* st4p = (const float4*)g_skelT;
    const int4*   t4   = (const int4*)targ;

    float a0=0.f, a1=0.f, a2=0.f, a3=0.f, a4=0.f, a5=0.f, a6=0.f;

    for (int v = blockIdx.x * RED_THREADS + threadIdx.x; v < NV;
         v += gridDim.x * RED_THREADS) {
        float4 p  = p4[v];
        float4 sp = sp4[v];
        float4 st = st4p[v];
        int4   ti = t4[v];
        float tx = (float)ti.x, ty = (float)ti.y, tz = (float)ti.z, tw = (float)ti.w;

        a0 += sp.x*tx + sp.y*ty + sp.z*tz + sp.w*tw;
        a1 += sp.x + sp.y + sp.z + sp.w;
        a2 += st.x*p.x + st.y*p.y + st.z*p.z + st.w*p.w;
        a3 += st.x + st.y + st.z + st.w;
        a4 += p.x*tx + p.y*ty + p.z*tz + p.w*tw;
        a5 += p.x + p.y + p.z + p.w;
        a6 += tx + ty + tz + tw;
    }

    #pragma unroll
    for (int off = 16; off > 0; off >>= 1) {
        a0 += __shfl_down_sync(0xFFFFFFFF, a0, off);
        a1 += __shfl_down_sync(0xFFFFFFFF, a1, off);
        a2 += __shfl_down_sync(0xFFFFFFFF, a2, off);
        a3 += __shfl_down_sync(0xFFFFFFFF, a3, off);
        a4 += __shfl_down_sync(0xFFFFFFFF, a4, off);
        a5 += __shfl_down_sync(0xFFFFFFFF, a5, off);
        a6 += __shfl_down_sync(0xFFFFFFFF, a6, off);
    }

    __shared__ double sacc[7][RED_THREADS/32];
    int warp = threadIdx.x >> 5, lane = threadIdx.x & 31;
    if (lane == 0) {
        sacc[0][warp]=a0; sacc[1][warp]=a1; sacc[2][warp]=a2;
        sacc[3][warp]=a3; sacc[4][warp]=a4; sacc[5][warp]=a5; sacc[6][warp]=a6;
    }
    __syncthreads();
    if (threadIdx.x < 7) {
        double s = 0.0;
        #pragma unroll
        for (int wv = 0; wv < RED_THREADS/32; wv++) s += sacc[threadIdx.x][wv];
        atomicAdd(&g_sums[threadIdx.x], s);
    }
}

__global__ void finalize_kernel(float* __restrict__ out)
{
    double S_spt=g_sums[0], S_sp=g_sums[1], S_stp=g_sums[2], S_st=g_sums[3];
    double S_pt =g_sums[4], S_p =g_sums[5], S_t =g_sums[6];
    const double SMOOTH = 1.0;
    double tprec = (S_spt + SMOOTH) / (S_sp + SMOOTH);
    double tsens = (S_stp + SMOOTH) / (S_st + SMOOTH);
    double cl    = 2.0 * tprec * tsens / (tprec + tsens + 1e-7);
    double dice  = (2.0 * S_pt + SMOOTH) / (S_p + S_t + SMOOTH);
    out[0] = (float)(1.0 - (0.5 * dice + 0.5 * cl));
}

// ---------------------------------------------------------------------------
// Launch
// ---------------------------------------------------------------------------
extern "C" void kernel_launch(void* const* d_in, const int* in_sizes, int n_in,
                              void* d_out, int out_size)
{
    const float* pred = (const float*)d_in[0];
    const int*   targ = (const int*)d_in[1];
    float* out = (float*)d_out;

    float *prob, *skelP, *skelT, *bufA, *bufB;
    cudaGetSymbolAddress((void**)&prob,  g_prob);
    cudaGetSymbolAddress((void**)&skelP, g_skelP);
    cudaGetSymbolAddress((void**)&skelT, g_skelT);
    cudaGetSymbolAddress((void**)&bufA,  g_bufA);
    cudaGetSymbolAddress((void**)&bufB,  g_bufB);

    dim3 grd(W / TW, H / TH, B);   // 16 x 64 x 8

    zero_sums<<<1, 32>>>();

    // ---- pred skeleton: init + 5 fused double-iterations ----
    init_kernel<true><<<grd, NT>>>(pred, nullptr, prob, skelP);
    {
        const float* in = prob;
        float* ob = bufB;
        for (int i = 0; i < 5; i++) {
            if (i < 4) iter2_kernel<true ><<<grd, NT>>>(in, ob, skelP);
            else       iter2_kernel<false><<<grd, NT>>>(in, ob, skelP);
            in = ob;
            ob = (ob == bufB) ? bufA : bufB;
        }
    }

    // ---- target skeleton ----
    init_kernel<false><<<grd, NT>>>(nullptr, targ, bufA, skelT);
    {
        const float* in = bufA;
        float* ob = bufB;
        for (int i = 0; i < 5; i++) {
            if (i < 4) iter2_kernel<true ><<<grd, NT>>>(in, ob, skelT);
            else       iter2_kernel<false><<<grd, NT>>>(in, ob, skelT);
            in = ob;
            ob = (ob == bufB) ? bufA : bufB;
        }
    }

    reduce_kernel<<<RED_BLOCKS, RED_THREADS>>>(targ);
    finalize_kernel<<<1, 1>>>(out);
}